// round 1
// baseline (speedup 1.0000x reference)
#include <cuda_runtime.h>
#include <math.h>

#define N_TOK 2048
#define DIM   1024
#define DE    512
#define DS    1024
#define NE    8

// -------- scratch (device globals; no allocations allowed) --------
__device__ float d_cw [N_TOK * 2];
__device__ int   d_cid[N_TOK * 2];
__device__ int   d_ecnt[NE];
__device__ int   d_eoff[NE];
__device__ int   d_etok[N_TOK * 2];
__device__ float d_ewt [N_TOK * 2];
__device__ int   d_slot[N_TOK * 2];
__device__ float d_Hs[N_TOK * DS];        // shared-expert hidden  (8 MB)
__device__ float d_Hr[N_TOK * 2 * DE];    // routed hidden, gathered by expert (8 MB)
__device__ float d_R [N_TOK * 2 * DIM];   // routed down output per slot (16 MB)

// ============================================================
// 1) gating: probs = softmax(x @ W_g), top-2 ids + weights
//    one block (256 thr) per token; warp w computes logit[w]
// ============================================================
__global__ void gate_kernel(const float* __restrict__ x, const float* __restrict__ Wg) {
    int n = blockIdx.x;
    __shared__ float xs[DIM];
    __shared__ float logits[NE];
    const float4* xr = (const float4*)(x + (size_t)n * DIM);
    float4* xs4 = (float4*)xs;
    if (threadIdx.x < 256) xs4[threadIdx.x] = xr[threadIdx.x];
    __syncthreads();
    int w = threadIdx.x >> 5, l = threadIdx.x & 31;
    float s = 0.f;
    for (int d = l; d < DIM; d += 32) s += xs[d] * Wg[d * NE + w];
    #pragma unroll
    for (int o = 16; o; o >>= 1) s += __shfl_xor_sync(0xffffffffu, s, o);
    if (l == 0) logits[w] = s;
    __syncthreads();
    if (threadIdx.x == 0) {
        float mx = logits[0];
        #pragma unroll
        for (int e = 1; e < NE; e++) mx = fmaxf(mx, logits[e]);
        float p[NE], den = 0.f;
        #pragma unroll
        for (int e = 0; e < NE; e++) { p[e] = expf(logits[e] - mx); den += p[e]; }
        float inv = 1.f / den;
        int i0 = 0;
        #pragma unroll
        for (int e = 1; e < NE; e++) if (p[e] > p[i0]) i0 = e;
        int i1 = (i0 == 0) ? 1 : 0;
        #pragma unroll
        for (int e = 0; e < NE; e++) if (e != i0 && p[e] > p[i1]) i1 = e;
        d_cid[2*n]   = i0; d_cw[2*n]   = p[i0] * inv;
        d_cid[2*n+1] = i1; d_cw[2*n+1] = p[i1] * inv;
    }
}

// ============================================================
// 2) build per-expert gather lists (single block)
// ============================================================
__global__ void build_kernel() {
    __shared__ int cnt[NE], off[NE], cur[NE];
    if (threadIdx.x < NE) cnt[threadIdx.x] = 0;
    __syncthreads();
    for (int s = threadIdx.x; s < N_TOK * 2; s += 256) atomicAdd(&cnt[d_cid[s]], 1);
    __syncthreads();
    if (threadIdx.x == 0) {
        int a = 0;
        for (int e = 0; e < NE; e++) { off[e] = a; cur[e] = a; a += cnt[e]; d_ecnt[e] = cnt[e]; d_eoff[e] = off[e]; }
    }
    __syncthreads();
    for (int s = threadIdx.x; s < N_TOK * 2; s += 256) {
        int e = d_cid[s];
        int slot = atomicAdd(&cur[e], 1);
        d_etok[slot] = s >> 1;
        d_ewt[slot]  = d_cw[s];
        d_slot[s]    = slot;
    }
}

// ---- GEMM tiling constants: 64x64x16 tile, 256 threads, 4x4 microtile ----
#define BM 64
#define BN 64
#define BK 16
#define APAD 68   // padded As row to dodge store bank conflicts (272B: 16B aligned)

__device__ __forceinline__ float silu(float g) { return g * (1.f / (1.f + expf(-g))); }

// ============================================================
// 3) shared expert gate+up fused:  Hs = silu(x@Wg_s) * (x@Wu_s)
//    A: x [2048 x 1024], B: [1024 x 1024] x2
// ============================================================
__global__ void shared_hidden_kernel(const float* __restrict__ x,
                                     const float* __restrict__ Wgs,
                                     const float* __restrict__ Wus) {
    __shared__ float As[BK][APAD];
    __shared__ float Bg[BK][BN];
    __shared__ float Bu[BK][BN];
    int n0 = blockIdx.x * BN;
    int m0 = blockIdx.y * BM;
    int tid = threadIdx.x;
    int tx = tid & 15, ty = tid >> 4;
    int arow = tid >> 2, ak = (tid & 3) * 4;
    int brow = tid >> 4, bc = (tid & 15) * 4;
    float ag[4][4] = {{0}}, au[4][4] = {{0}};
    for (int k0 = 0; k0 < DIM; k0 += BK) {
        float4 av = *(const float4*)(x + (size_t)(m0 + arow) * DIM + k0 + ak);
        As[ak+0][arow] = av.x; As[ak+1][arow] = av.y; As[ak+2][arow] = av.z; As[ak+3][arow] = av.w;
        *(float4*)&Bg[brow][bc] = *(const float4*)(Wgs + (size_t)(k0 + brow) * DS + n0 + bc);
        *(float4*)&Bu[brow][bc] = *(const float4*)(Wus + (size_t)(k0 + brow) * DS + n0 + bc);
        __syncthreads();
        #pragma unroll
        for (int k = 0; k < BK; k++) {
            float4 a  = *(const float4*)&As[k][ty * 4];
            float4 bg = *(const float4*)&Bg[k][tx * 4];
            float4 bu = *(const float4*)&Bu[k][tx * 4];
            float aa[4] = {a.x, a.y, a.z, a.w};
            float gg[4] = {bg.x, bg.y, bg.z, bg.w};
            float uu[4] = {bu.x, bu.y, bu.z, bu.w};
            #pragma unroll
            for (int i = 0; i < 4; i++)
                #pragma unroll
                for (int j = 0; j < 4; j++) { ag[i][j] += aa[i] * gg[j]; au[i][j] += aa[i] * uu[j]; }
        }
        __syncthreads();
    }
    #pragma unroll
    for (int i = 0; i < 4; i++) {
        float4 o;
        o.x = silu(ag[i][0]) * au[i][0];
        o.y = silu(ag[i][1]) * au[i][1];
        o.z = silu(ag[i][2]) * au[i][2];
        o.w = silu(ag[i][3]) * au[i][3];
        *(float4*)(d_Hs + (size_t)(m0 + ty * 4 + i) * DS + n0 + tx * 4) = o;
    }
}

// ============================================================
// 4) shared down: out = Hs @ Wd_s   [2048x1024]@[1024x1024]
// ============================================================
__global__ void shared_down_kernel(const float* __restrict__ Wds, float* __restrict__ out) {
    __shared__ float As[BK][APAD];
    __shared__ float Bs[BK][BN];
    int n0 = blockIdx.x * BN;
    int m0 = blockIdx.y * BM;
    int tid = threadIdx.x;
    int tx = tid & 15, ty = tid >> 4;
    int arow = tid >> 2, ak = (tid & 3) * 4;
    int brow = tid >> 4, bc = (tid & 15) * 4;
    float acc[4][4] = {{0}};
    for (int k0 = 0; k0 < DS; k0 += BK) {
        float4 av = *(const float4*)(d_Hs + (size_t)(m0 + arow) * DS + k0 + ak);
        As[ak+0][arow] = av.x; As[ak+1][arow] = av.y; As[ak+2][arow] = av.z; As[ak+3][arow] = av.w;
        *(float4*)&Bs[brow][bc] = *(const float4*)(Wds + (size_t)(k0 + brow) * DIM + n0 + bc);
        __syncthreads();
        #pragma unroll
        for (int k = 0; k < BK; k++) {
            float4 a = *(const float4*)&As[k][ty * 4];
            float4 b = *(const float4*)&Bs[k][tx * 4];
            float aa[4] = {a.x, a.y, a.z, a.w};
            float bb[4] = {b.x, b.y, b.z, b.w};
            #pragma unroll
            for (int i = 0; i < 4; i++)
                #pragma unroll
                for (int j = 0; j < 4; j++) acc[i][j] += aa[i] * bb[j];
        }
        __syncthreads();
    }
    #pragma unroll
    for (int i = 0; i < 4; i++) {
        float4 o; o.x = acc[i][0]; o.y = acc[i][1]; o.z = acc[i][2]; o.w = acc[i][3];
        *(float4*)(out + (size_t)(m0 + ty * 4 + i) * DIM + n0 + tx * 4) = o;
    }
}

// ============================================================
// 5) routed gate+up, gathered per expert; fold combine weight
//    Hr[slot] = w_slot * silu(x[tok]@Wg_e[e]) * (x[tok]@Wu_e[e])
// ============================================================
__global__ void routed_hidden_kernel(const float* __restrict__ x,
                                     const float* __restrict__ Wge,
                                     const float* __restrict__ Wue) {
    int e = blockIdx.z;
    int cnt = d_ecnt[e], off = d_eoff[e];
    int m0 = blockIdx.y * BM;
    if (m0 >= cnt) return;
    __shared__ int   rows[BM];
    __shared__ float As[BK][APAD];
    __shared__ float Bg[BK][BN];
    __shared__ float Bu[BK][BN];
    int tid = threadIdx.x;
    if (tid < BM) {
        int m = m0 + tid;
        rows[tid] = (m < cnt) ? d_etok[off + m] : -1;
    }
    __syncthreads();
    const float* Wg = Wge + (size_t)e * DIM * DE;
    const float* Wu = Wue + (size_t)e * DIM * DE;
    int n0 = blockIdx.x * BN;
    int tx = tid & 15, ty = tid >> 4;
    int arow = tid >> 2, ak = (tid & 3) * 4;
    int brow = tid >> 4, bc = (tid & 15) * 4;
    float ag[4][4] = {{0}}, au[4][4] = {{0}};
    for (int k0 = 0; k0 < DIM; k0 += BK) {
        int r = rows[arow];
        float4 av = make_float4(0.f, 0.f, 0.f, 0.f);
        if (r >= 0) av = *(const float4*)(x + (size_t)r * DIM + k0 + ak);
        As[ak+0][arow] = av.x; As[ak+1][arow] = av.y; As[ak+2][arow] = av.z; As[ak+3][arow] = av.w;
        *(float4*)&Bg[brow][bc] = *(const float4*)(Wg + (size_t)(k0 + brow) * DE + n0 + bc);
        *(float4*)&Bu[brow][bc] = *(const float4*)(Wu + (size_t)(k0 + brow) * DE + n0 + bc);
        __syncthreads();
        #pragma unroll
        for (int k = 0; k < BK; k++) {
            float4 a  = *(const float4*)&As[k][ty * 4];
            float4 bg = *(const float4*)&Bg[k][tx * 4];
            float4 bu = *(const float4*)&Bu[k][tx * 4];
            float aa[4] = {a.x, a.y, a.z, a.w};
            float gg[4] = {bg.x, bg.y, bg.z, bg.w};
            float uu[4] = {bu.x, bu.y, bu.z, bu.w};
            #pragma unroll
            for (int i = 0; i < 4; i++)
                #pragma unroll
                for (int j = 0; j < 4; j++) { ag[i][j] += aa[i] * gg[j]; au[i][j] += aa[i] * uu[j]; }
        }
        __syncthreads();
    }
    #pragma unroll
    for (int i = 0; i < 4; i++) {
        int m = m0 + ty * 4 + i;
        if (m < cnt) {
            int slot = off + m;
            float wt = d_ewt[slot];
            float4 o;
            o.x = silu(ag[i][0]) * au[i][0] * wt;
            o.y = silu(ag[i][1]) * au[i][1] * wt;
            o.z = silu(ag[i][2]) * au[i][2] * wt;
            o.w = silu(ag[i][3]) * au[i][3] * wt;
            *(float4*)(d_Hr + (size_t)slot * DE + n0 + tx * 4) = o;
        }
    }
}

// ============================================================
// 6) routed down, gathered:  R[slot] = Hr[slot] @ Wd_e[e]
// ============================================================
__global__ void routed_down_kernel(const float* __restrict__ Wde) {
    int e = blockIdx.z;
    int cnt = d_ecnt[e], off = d_eoff[e];
    int m0 = blockIdx.y * BM;
    if (m0 >= cnt) return;
    __shared__ float As[BK][APAD];
    __shared__ float Bs[BK][BN];
    const float* Wd = Wde + (size_t)e * DE * DIM;
    int n0 = blockIdx.x * BN;
    int tid = threadIdx.x;
    int tx = tid & 15, ty = tid >> 4;
    int arow = tid >> 2, ak = (tid & 3) * 4;
    int brow = tid >> 4, bc = (tid & 15) * 4;
    float acc[4][4] = {{0}};
    for (int k0 = 0; k0 < DE; k0 += BK) {
        int m = m0 + arow;
        float4 av = make_float4(0.f, 0.f, 0.f, 0.f);
        if (m < cnt) av = *(const float4*)(d_Hr + (size_t)(off + m) * DE + k0 + ak);
        As[ak+0][arow] = av.x; As[ak+1][arow] = av.y; As[ak+2][arow] = av.z; As[ak+3][arow] = av.w;
        *(float4*)&Bs[brow][bc] = *(const float4*)(Wd + (size_t)(k0 + brow) * DIM + n0 + bc);
        __syncthreads();
        #pragma unroll
        for (int k = 0; k < BK; k++) {
            float4 a = *(const float4*)&As[k][ty * 4];
            float4 b = *(const float4*)&Bs[k][tx * 4];
            float aa[4] = {a.x, a.y, a.z, a.w};
            float bb[4] = {b.x, b.y, b.z, b.w};
            #pragma unroll
            for (int i = 0; i < 4; i++)
                #pragma unroll
                for (int j = 0; j < 4; j++) acc[i][j] += aa[i] * bb[j];
        }
        __syncthreads();
    }
    #pragma unroll
    for (int i = 0; i < 4; i++) {
        int m = m0 + ty * 4 + i;
        if (m < cnt) {
            float4 o; o.x = acc[i][0]; o.y = acc[i][1]; o.z = acc[i][2]; o.w = acc[i][3];
            *(float4*)(d_R + (size_t)(off + m) * DIM + n0 + tx * 4) = o;
        }
    }
}

// ============================================================
// 7) combine: out[n] += R[slot(n,0)] + R[slot(n,1)]
// ============================================================
__global__ void combine_kernel(float* __restrict__ out) {
    int n = blockIdx.x;
    int t = threadIdx.x;                     // 256 threads * float4 = 1024 floats
    int s0 = d_slot[2 * n], s1 = d_slot[2 * n + 1];
    float4* o4 = (float4*)(out + (size_t)n * DIM);
    const float4* r0 = (const float4*)(d_R + (size_t)s0 * DIM);
    const float4* r1 = (const float4*)(d_R + (size_t)s1 * DIM);
    float4 a = o4[t], b = r0[t], c = r1[t];
    a.x += b.x + c.x; a.y += b.y + c.y; a.z += b.z + c.z; a.w += b.w + c.w;
    o4[t] = a;
}

// ============================================================
extern "C" void kernel_launch(void* const* d_in, const int* in_sizes, int n_in,
                              void* d_out, int out_size) {
    const float* x   = (const float*)d_in[0];
    const float* Wg  = (const float*)d_in[1];
    const float* Wge = (const float*)d_in[2];
    const float* Wue = (const float*)d_in[3];
    const float* Wde = (const float*)d_in[4];
    const float* Wgs = (const float*)d_in[5];
    const float* Wus = (const float*)d_in[6];
    const float* Wds = (const float*)d_in[7];
    float* out = (float*)d_out;

    gate_kernel<<<N_TOK, 256>>>(x, Wg);
    build_kernel<<<1, 256>>>();
    shared_hidden_kernel<<<dim3(DS / BN, N_TOK / BM), 256>>>(x, Wgs, Wus);
    shared_down_kernel<<<dim3(DIM / BN, N_TOK / BM), 256>>>(Wds, out);
    routed_hidden_kernel<<<dim3(DE / BN, N_TOK / BM, NE), 256>>>(x, Wge, Wue);
    routed_down_kernel<<<dim3(DIM / BN, N_TOK / BM, NE), 256>>>(Wde);
    combine_kernel<<<N_TOK, 256>>>(out);
}

// round 3
// speedup vs baseline: 2.2743x; 2.2743x over previous
#include <cuda_runtime.h>
#include <cuda_bf16.h>
#include <math.h>
#include <stdint.h>

#define N_TOK 2048
#define DIM   1024
#define DE    512
#define DS    1024
#define NE    8
#define NSLOT (N_TOK * 2)

// ----------------- scratch (device globals; no allocs) -----------------
__device__ float d_cw [NSLOT];
__device__ int   d_cid[NSLOT];
__device__ int   d_ecnt[NE];
__device__ int   d_eoff[NE];
__device__ int   d_etok[NSLOT];
__device__ float d_ewt [NSLOT];
__device__ int   d_slot[NSLOT];

__device__ __nv_bfloat16 d_xh[N_TOK * DIM],  d_xl[N_TOK * DIM];
__device__ __nv_bfloat16 d_Wgs_h[DS * DIM],  d_Wgs_l[DS * DIM];   // [N=DS][K=DIM]
__device__ __nv_bfloat16 d_Wus_h[DS * DIM],  d_Wus_l[DS * DIM];
__device__ __nv_bfloat16 d_Wds_h[DIM * DS],  d_Wds_l[DIM * DS];   // [N=DIM][K=DS]
__device__ __nv_bfloat16 d_Wge_h[NE * DE * DIM], d_Wge_l[NE * DE * DIM]; // [e][N=DE][K=DIM]
__device__ __nv_bfloat16 d_Wue_h[NE * DE * DIM], d_Wue_l[NE * DE * DIM];
__device__ __nv_bfloat16 d_Wde_h[NE * DIM * DE], d_Wde_l[NE * DIM * DE]; // [e][N=DIM][K=DE]

__device__ float d_Gs[N_TOK * DS];
__device__ float d_Us[N_TOK * DS];
__device__ __nv_bfloat16 d_Hs_h[N_TOK * DS], d_Hs_l[N_TOK * DS];
__device__ float d_Gr[NSLOT * DE];
__device__ float d_Ur[NSLOT * DE];
__device__ __nv_bfloat16 d_Hr_h[NSLOT * DE], d_Hr_l[NSLOT * DE];
__device__ float d_R [NSLOT * DIM];

// ----------------- asm helpers (base-target only: sm_80-class) -----------------
__device__ __forceinline__ uint32_t sm2u32(const void* p) {
    uint32_t a;
    asm("{ .reg .u64 t; cvta.to.shared.u64 t, %1; cvt.u32.u64 %0, t; }" : "=r"(a) : "l"(p));
    return a;
}
#define SWZ(o) ((o) ^ (((o) >> 3) & 0x70))

#define CPA16(s, g)  asm volatile("cp.async.cg.shared.global [%0], [%1], 16;" :: "r"(s), "l"(g))
#define CPCOMMIT()   asm volatile("cp.async.commit_group;" ::: "memory")
#define CPWAIT1()    asm volatile("cp.async.wait_group 1;" ::: "memory")
#define CPWAIT0()    asm volatile("cp.async.wait_group 0;" ::: "memory")

#define LDMX4(r, a) \
    asm volatile("ldmatrix.sync.aligned.m8n8.x4.shared.b16 {%0,%1,%2,%3}, [%4];" \
        : "=r"((r)[0]), "=r"((r)[1]), "=r"((r)[2]), "=r"((r)[3]) : "r"(a))

#define MMA16816(c, a, b0, b1) \
    asm volatile("mma.sync.aligned.m16n8k16.row.col.f32.bf16.bf16.f32 " \
        "{%0,%1,%2,%3},{%4,%5,%6,%7},{%8,%9},{%0,%1,%2,%3};" \
        : "+f"((c)[0]), "+f"((c)[1]), "+f"((c)[2]), "+f"((c)[3]) \
        : "r"((a)[0]), "r"((a)[1]), "r"((a)[2]), "r"((a)[3]), "r"(b0), "r"(b1))

// ----------------- small kernels -----------------
__global__ void gate_kernel(const float* __restrict__ x, const float* __restrict__ Wg) {
    int n = blockIdx.x;
    __shared__ float xs[DIM];
    __shared__ float logits[NE];
    const float4* xr = (const float4*)(x + (size_t)n * DIM);
    ((float4*)xs)[threadIdx.x] = xr[threadIdx.x];
    __syncthreads();
    int w = threadIdx.x >> 5, l = threadIdx.x & 31;
    float s = 0.f;
    for (int d = l; d < DIM; d += 32) s += xs[d] * Wg[d * NE + w];
    #pragma unroll
    for (int o = 16; o; o >>= 1) s += __shfl_xor_sync(0xffffffffu, s, o);
    if (l == 0) logits[w] = s;
    __syncthreads();
    if (threadIdx.x == 0) {
        float mx = logits[0];
        #pragma unroll
        for (int e = 1; e < NE; e++) mx = fmaxf(mx, logits[e]);
        float p[NE], den = 0.f;
        #pragma unroll
        for (int e = 0; e < NE; e++) { p[e] = expf(logits[e] - mx); den += p[e]; }
        float inv = 1.f / den;
        int i0 = 0;
        #pragma unroll
        for (int e = 1; e < NE; e++) if (p[e] > p[i0]) i0 = e;
        int i1 = (i0 == 0) ? 1 : 0;
        #pragma unroll
        for (int e = 0; e < NE; e++) if (e != i0 && p[e] > p[i1]) i1 = e;
        d_cid[2*n]   = i0; d_cw[2*n]   = p[i0] * inv;
        d_cid[2*n+1] = i1; d_cw[2*n+1] = p[i1] * inv;
    }
}

__global__ void build_kernel() {
    __shared__ int cnt[NE], off[NE], cur[NE];
    if (threadIdx.x < NE) cnt[threadIdx.x] = 0;
    __syncthreads();
    for (int s = threadIdx.x; s < NSLOT; s += 256) atomicAdd(&cnt[d_cid[s]], 1);
    __syncthreads();
    if (threadIdx.x == 0) {
        int a = 0;
        for (int e = 0; e < NE; e++) { off[e] = a; cur[e] = a; a += cnt[e]; d_ecnt[e] = cnt[e]; d_eoff[e] = off[e]; }
    }
    __syncthreads();
    for (int s = threadIdx.x; s < NSLOT; s += 256) {
        int e = d_cid[s];
        int slot = atomicAdd(&cur[e], 1);
        d_etok[slot] = s >> 1;
        d_ewt[slot]  = d_cw[s];
        d_slot[s]    = slot;
    }
}

__device__ __forceinline__ void split2(float v, __nv_bfloat16& h, __nv_bfloat16& l) {
    h = __float2bfloat16(v);
    l = __float2bfloat16(v - __bfloat162float(h));
}

__global__ void convX(const float* __restrict__ x, __nv_bfloat16* __restrict__ xh,
                      __nv_bfloat16* __restrict__ xl, int n4) {
    int i = blockIdx.x * blockDim.x + threadIdx.x;
    if (i >= n4) return;
    float4 v = ((const float4*)x)[i];
    __nv_bfloat16 h0,h1,h2,h3,l0,l1,l2,l3;
    split2(v.x,h0,l0); split2(v.y,h1,l1); split2(v.z,h2,l2); split2(v.w,h3,l3);
    __nv_bfloat162* ph = (__nv_bfloat162*)xh;
    __nv_bfloat162* pl = (__nv_bfloat162*)xl;
    __nv_bfloat162 a; a.x=h0; a.y=h1; __nv_bfloat162 b; b.x=h2; b.y=h3;
    ph[2*i] = a; ph[2*i+1] = b;
    a.x=l0; a.y=l1; b.x=l2; b.y=l3;
    pl[2*i] = a; pl[2*i+1] = b;
}

// W [K][N] fp32 -> transposed bf16 hi/lo [N][K]
__global__ void convT(const float* __restrict__ src, __nv_bfloat16* __restrict__ dh,
                      __nv_bfloat16* __restrict__ dl, int K, int N,
                      size_t sBatch, size_t dBatch) {
    int b = blockIdx.z;
    src += (size_t)b * sBatch; dh += (size_t)b * dBatch; dl += (size_t)b * dBatch;
    __shared__ float t[32][33];
    int k0 = blockIdx.y * 32, n0 = blockIdx.x * 32;
    int tx = threadIdx.x, ty = threadIdx.y;
    #pragma unroll
    for (int i = 0; i < 32; i += 8) t[ty + i][tx] = src[(size_t)(k0 + ty + i) * N + n0 + tx];
    __syncthreads();
    #pragma unroll
    for (int i = 0; i < 32; i += 8) {
        float v = t[tx][ty + i];
        __nv_bfloat16 h, l; split2(v, h, l);
        size_t o = (size_t)(n0 + ty + i) * K + k0 + tx;
        dh[o] = h; dl[o] = l;
    }
}

__device__ __forceinline__ float silu(float g) { return g * (1.f / (1.f + expf(-g))); }

__global__ void ew_shared(int n4) {
    int i = blockIdx.x * blockDim.x + threadIdx.x;
    if (i >= n4) return;
    float4 g = ((const float4*)d_Gs)[i];
    float4 u = ((const float4*)d_Us)[i];
    float4 h;
    h.x = silu(g.x)*u.x; h.y = silu(g.y)*u.y; h.z = silu(g.z)*u.z; h.w = silu(g.w)*u.w;
    __nv_bfloat16 h0,h1,h2,h3,l0,l1,l2,l3;
    split2(h.x,h0,l0); split2(h.y,h1,l1); split2(h.z,h2,l2); split2(h.w,h3,l3);
    __nv_bfloat162* ph = (__nv_bfloat162*)d_Hs_h;
    __nv_bfloat162* pl = (__nv_bfloat162*)d_Hs_l;
    __nv_bfloat162 a; a.x=h0; a.y=h1; __nv_bfloat162 b; b.x=h2; b.y=h3;
    ph[2*i]=a; ph[2*i+1]=b;
    a.x=l0; a.y=l1; b.x=l2; b.y=l3;
    pl[2*i]=a; pl[2*i+1]=b;
}

__global__ void ew_routed(int n4) {
    int i = blockIdx.x * blockDim.x + threadIdx.x;
    if (i >= n4) return;
    int slot = (i * 4) / DE;
    float wt = d_ewt[slot];
    float4 g = ((const float4*)d_Gr)[i];
    float4 u = ((const float4*)d_Ur)[i];
    float4 h;
    h.x = wt*silu(g.x)*u.x; h.y = wt*silu(g.y)*u.y; h.z = wt*silu(g.z)*u.z; h.w = wt*silu(g.w)*u.w;
    __nv_bfloat16 h0,h1,h2,h3,l0,l1,l2,l3;
    split2(h.x,h0,l0); split2(h.y,h1,l1); split2(h.z,h2,l2); split2(h.w,h3,l3);
    __nv_bfloat162* ph = (__nv_bfloat162*)d_Hr_h;
    __nv_bfloat162* pl = (__nv_bfloat162*)d_Hr_l;
    __nv_bfloat162 a; a.x=h0; a.y=h1; __nv_bfloat162 b; b.x=h2; b.y=h3;
    ph[2*i]=a; ph[2*i+1]=b;
    a.x=l0; a.y=l1; b.x=l2; b.y=l3;
    pl[2*i]=a; pl[2*i+1]=b;
}

__global__ void combine_kernel(float* __restrict__ out) {
    int n = blockIdx.x;
    int t = threadIdx.x;
    int s0 = d_slot[2 * n], s1 = d_slot[2 * n + 1];
    float4* o4 = (float4*)(out + (size_t)n * DIM);
    const float4* r0 = (const float4*)(d_R + (size_t)s0 * DIM);
    const float4* r1 = (const float4*)(d_R + (size_t)s1 * DIM);
    float4 a = o4[t], b = r0[t], c = r1[t];
    a.x += b.x + c.x; a.y += b.y + c.y; a.z += b.z + c.z; a.w += b.w + c.w;
    o4[t] = a;
}

// ----------------- HMMA split-bf16 GEMM (mma.sync, base target) -----------------
// C[m][n] = sum_k A[m][k]*B[n][k], A=Ah+Al, B=Bh+Bl (drop Al*Bl)
// tile 128x128x64; 256 thr; warp grid 2x4 -> warp tile 64x32; 2-stage cp.async
#define GBM 128
#define GBN 128
#define GBK 64
#define STG 65536                 // bytes per stage: 4 bufs x 16KB
#define BUF_AH 0
#define BUF_AL 16384
#define BUF_BH 32768
#define BUF_BL 49152
#define SM_TOT2 (2 * STG)

// mode 0: dense, z selects (B0,C0)/(B1,C1)
// mode 1: routed gather (A rows via d_etok), z = e + 8*sel
// mode 2: routed identity (A rows = slots), z = e
__global__ void __launch_bounds__(256) gemm_hmma(
    const __nv_bfloat16* __restrict__ Ah, const __nv_bfloat16* __restrict__ Al, int lda,
    const __nv_bfloat16* __restrict__ B0h, const __nv_bfloat16* __restrict__ B0l,
    const __nv_bfloat16* __restrict__ B1h, const __nv_bfloat16* __restrict__ B1l,
    float* __restrict__ C0, float* __restrict__ C1, int ldc,
    int N, int K, int mode)
{
    extern __shared__ char sm[];
    int tid = threadIdx.x, lane = tid & 31, wid = tid >> 5;
    int wm = wid >> 2, wn = wid & 3;
    int m0 = blockIdx.y * GBM;

    const __nv_bfloat16 *Bh, *Bl;
    float* C;
    int mValid, cRowBase, aRowLd;
    int ldRow = tid >> 1, ldHalf = tid & 1;

    if (mode == 0) {
        int sel = blockIdx.z;
        Bh = sel ? B1h : B0h; Bl = sel ? B1l : B0l; C = sel ? C1 : C0;
        mValid = GBM; cRowBase = m0;
        aRowLd = m0 + ldRow;
    } else {
        int e   = (mode == 1) ? (blockIdx.z & 7) : blockIdx.z;
        int sel = (mode == 1) ? (blockIdx.z >> 3) : 0;
        int cnt = d_ecnt[e], off = d_eoff[e];
        if (m0 >= cnt) return;
        Bh = (sel ? B1h : B0h) + (size_t)e * N * K;
        Bl = (sel ? B1l : B0l) + (size_t)e * N * K;
        C  = sel ? C1 : C0;
        mValid = cnt - m0; if (mValid > GBM) mValid = GBM;
        cRowBase = off + m0;
        int m = m0 + ldRow; if (m > cnt - 1) m = cnt - 1;
        aRowLd = (mode == 1) ? d_etok[off + m] : (off + m);
    }
    int n0 = blockIdx.x * GBN;
    Bh += (size_t)n0 * K;
    Bl += (size_t)n0 * K;

    uint32_t sbase = sm2u32(sm);

    const char* aGh = (const char*)(Ah + (size_t)aRowLd * lda);
    const char* aGl = (const char*)(Al + (size_t)aRowLd * lda);
    const char* bGh = (const char*)(Bh + (size_t)ldRow * K);
    const char* bGl = (const char*)(Bl + (size_t)ldRow * K);
    uint32_t soff[4];
    #pragma unroll
    for (int i = 0; i < 4; i++) soff[i] = SWZ((uint32_t)(ldRow * 128 + ldHalf * 64 + i * 16));
    int gOffBase = ldHalf * 64;   // byte offset inside 128B k-chunk row

    int nChunks = K / GBK;

    // prologue: stage 0
    {
        size_t gk = gOffBase;
        uint32_t sb = sbase;
        #pragma unroll
        for (int i = 0; i < 4; i++) {
            size_t g = gk + i * 16;
            CPA16(sb + BUF_AH + soff[i], aGh + g);
            CPA16(sb + BUF_AL + soff[i], aGl + g);
            CPA16(sb + BUF_BH + soff[i], bGh + g);
            CPA16(sb + BUF_BL + soff[i], bGl + g);
        }
        CPCOMMIT();
    }

    float acc[4][4][4];
    #pragma unroll
    for (int a = 0; a < 4; a++)
        #pragma unroll
        for (int b = 0; b < 4; b++)
            #pragma unroll
            for (int cR = 0; cR < 4; cR++) acc[a][b][cR] = 0.f;

    int aRowB = wm * 64 + (lane & 15);
    int aColH = (lane >> 4) * 8;
    int bRowB = wn * 32 + (lane & 7) + ((lane >> 4) << 3);
    int bColH = ((lane >> 3) & 1) * 8;

    for (int c = 0; c < nChunks; c++) {
        int st = c & 1;
        if (c + 1 < nChunks) {
            size_t gk = (size_t)(c + 1) * 128 + gOffBase;
            uint32_t sb = sbase + (st ^ 1) * STG;
            #pragma unroll
            for (int i = 0; i < 4; i++) {
                size_t g = gk + i * 16;
                CPA16(sb + BUF_AH + soff[i], aGh + g);
                CPA16(sb + BUF_AL + soff[i], aGl + g);
                CPA16(sb + BUF_BH + soff[i], bGh + g);
                CPA16(sb + BUF_BL + soff[i], bGl + g);
            }
            CPCOMMIT();
            CPWAIT1();
        } else {
            CPWAIT0();
        }
        __syncthreads();

        uint32_t sb = sbase + st * STG;
        #pragma unroll
        for (int ks = 0; ks < 4; ks++) {
            uint32_t ah[4][4], al[4][4], bh[2][4], bl[2][4];
            #pragma unroll
            for (int mt = 0; mt < 4; mt++) {
                uint32_t byte = (uint32_t)((aRowB + mt * 16) * 128 + (ks * 16 + aColH) * 2);
                uint32_t sw = SWZ(byte);
                LDMX4(ah[mt], sb + BUF_AH + sw);
                LDMX4(al[mt], sb + BUF_AL + sw);
            }
            #pragma unroll
            for (int g = 0; g < 2; g++) {
                uint32_t byte = (uint32_t)((bRowB + g * 16) * 128 + (ks * 16 + bColH) * 2);
                uint32_t sw = SWZ(byte);
                LDMX4(bh[g], sb + BUF_BH + sw);
                LDMX4(bl[g], sb + BUF_BL + sw);
            }
            #pragma unroll
            for (int mt = 0; mt < 4; mt++) {
                #pragma unroll
                for (int n8 = 0; n8 < 4; n8++) {
                    int g = n8 >> 1, j = (n8 & 1) * 2;
                    MMA16816(acc[mt][n8], ah[mt], bh[g][j], bh[g][j + 1]);
                    MMA16816(acc[mt][n8], ah[mt], bl[g][j], bl[g][j + 1]);
                    MMA16816(acc[mt][n8], al[mt], bh[g][j], bh[g][j + 1]);
                }
            }
        }
        __syncthreads();
    }

    // epilogue: fp32 stores (float2 per n8 tile per half)
    #pragma unroll
    for (int mt = 0; mt < 4; mt++) {
        #pragma unroll
        for (int h = 0; h < 2; h++) {
            int rIn = wm * 64 + mt * 16 + (lane >> 2) + h * 8;
            if (rIn < mValid) {
                float* p = C + (size_t)(cRowBase + rIn) * ldc + n0 + wn * 32 + (lane & 3) * 2;
                #pragma unroll
                for (int n8 = 0; n8 < 4; n8++) {
                    float2 v; v.x = acc[mt][n8][h * 2 + 0]; v.y = acc[mt][n8][h * 2 + 1];
                    *(float2*)(p + n8 * 8) = v;
                }
            }
        }
    }
}

// ----------------- launch -----------------
extern "C" void kernel_launch(void* const* d_in, const int* in_sizes, int n_in,
                              void* d_out, int out_size) {
    const float* x   = (const float*)d_in[0];
    const float* Wg  = (const float*)d_in[1];
    const float* Wge = (const float*)d_in[2];
    const float* Wue = (const float*)d_in[3];
    const float* Wde = (const float*)d_in[4];
    const float* Wgs = (const float*)d_in[5];
    const float* Wus = (const float*)d_in[6];
    const float* Wds = (const float*)d_in[7];
    float* out = (float*)d_out;

    cudaFuncSetAttribute(gemm_hmma, cudaFuncAttributeMaxDynamicSharedMemorySize, SM_TOT2);

    __nv_bfloat16 *xh, *xl, *wgsh, *wgsl, *wush, *wusl, *wdsh, *wdsl;
    __nv_bfloat16 *wgeh, *wgel, *wueh, *wuel, *wdeh, *wdel;
    __nv_bfloat16 *hsh, *hsl, *hrh, *hrl;
    float *gs, *us, *gr, *ur, *rr;
    cudaGetSymbolAddress((void**)&xh, d_xh);   cudaGetSymbolAddress((void**)&xl, d_xl);
    cudaGetSymbolAddress((void**)&wgsh, d_Wgs_h); cudaGetSymbolAddress((void**)&wgsl, d_Wgs_l);
    cudaGetSymbolAddress((void**)&wush, d_Wus_h); cudaGetSymbolAddress((void**)&wusl, d_Wus_l);
    cudaGetSymbolAddress((void**)&wdsh, d_Wds_h); cudaGetSymbolAddress((void**)&wdsl, d_Wds_l);
    cudaGetSymbolAddress((void**)&wgeh, d_Wge_h); cudaGetSymbolAddress((void**)&wgel, d_Wge_l);
    cudaGetSymbolAddress((void**)&wueh, d_Wue_h); cudaGetSymbolAddress((void**)&wuel, d_Wue_l);
    cudaGetSymbolAddress((void**)&wdeh, d_Wde_h); cudaGetSymbolAddress((void**)&wdel, d_Wde_l);
    cudaGetSymbolAddress((void**)&hsh, d_Hs_h); cudaGetSymbolAddress((void**)&hsl, d_Hs_l);
    cudaGetSymbolAddress((void**)&hrh, d_Hr_h); cudaGetSymbolAddress((void**)&hrl, d_Hr_l);
    cudaGetSymbolAddress((void**)&gs, d_Gs); cudaGetSymbolAddress((void**)&us, d_Us);
    cudaGetSymbolAddress((void**)&gr, d_Gr); cudaGetSymbolAddress((void**)&ur, d_Ur);
    cudaGetSymbolAddress((void**)&rr, d_R);

    // conversions (split-bf16 + weight transposes)
    convX<<<(N_TOK * DIM / 4 + 255) / 256, 256>>>(x, xh, xl, N_TOK * DIM / 4);
    convT<<<dim3(DS / 32, DIM / 32, 1), dim3(32, 8)>>>(Wgs, wgsh, wgsl, DIM, DS, 0, 0);
    convT<<<dim3(DS / 32, DIM / 32, 1), dim3(32, 8)>>>(Wus, wush, wusl, DIM, DS, 0, 0);
    convT<<<dim3(DIM / 32, DS / 32, 1), dim3(32, 8)>>>(Wds, wdsh, wdsl, DS, DIM, 0, 0);
    convT<<<dim3(DE / 32, DIM / 32, NE), dim3(32, 8)>>>(Wge, wgeh, wgel, DIM, DE, (size_t)DIM * DE, (size_t)DE * DIM);
    convT<<<dim3(DE / 32, DIM / 32, NE), dim3(32, 8)>>>(Wue, wueh, wuel, DIM, DE, (size_t)DIM * DE, (size_t)DE * DIM);
    convT<<<dim3(DIM / 32, DE / 32, NE), dim3(32, 8)>>>(Wde, wdeh, wdel, DE, DIM, (size_t)DE * DIM, (size_t)DIM * DE);

    gate_kernel<<<N_TOK, 256>>>(x, Wg);
    build_kernel<<<1, 256>>>();

    // shared gate+up: Gs = x@Wgs, Us = x@Wus
    gemm_hmma<<<dim3(DS / GBN, N_TOK / GBM, 2), 256, SM_TOT2>>>(
        xh, xl, DIM, wgsh, wgsl, wush, wusl, gs, us, DS, DS, DIM, 0);
    ew_shared<<<(N_TOK * DS / 4 + 255) / 256, 256>>>(N_TOK * DS / 4);

    // shared down: out = Hs@Wds
    gemm_hmma<<<dim3(DIM / GBN, N_TOK / GBM, 1), 256, SM_TOT2>>>(
        hsh, hsl, DS, wdsh, wdsl, wdsh, wdsl, out, out, DIM, DIM, DS, 0);

    // routed gate+up (gathered): Gr/Ur[slot] = x[tok]@Wge/Wue[e]
    gemm_hmma<<<dim3(DE / GBN, NSLOT / GBM, 2 * NE), 256, SM_TOT2>>>(
        xh, xl, DIM, wgeh, wgel, wueh, wuel, gr, ur, DE, DE, DIM, 1);
    ew_routed<<<(NSLOT * DE / 4 + 255) / 256, 256>>>(NSLOT * DE / 4);

    // routed down: R[slot] = Hr[slot]@Wde[e]
    gemm_hmma<<<dim3(DIM / GBN, NSLOT / GBM, NE), 256, SM_TOT2>>>(
        hrh, hrl, DE, wdeh, wdel, wdeh, wdel, rr, rr, DIM, DIM, DE, 2);

    combine_kernel<<<N_TOK, 256>>>(out);
}

// round 4
// speedup vs baseline: 2.5137x; 1.1053x over previous
#include <cuda_runtime.h>
#include <cuda_bf16.h>
#include <math.h>
#include <stdint.h>

#define N_TOK 2048
#define DIM   1024
#define DE    512
#define DS    1024
#define NE    8
#define NSLOT (N_TOK * 2)

// ----------------- scratch (device globals; no allocs) -----------------
__device__ float d_cw [NSLOT];
__device__ int   d_cid[NSLOT];
__device__ int   d_ecnt[NE];
__device__ int   d_eoff[NE];
__device__ int   d_etok[NSLOT];
__device__ float d_ewt [NSLOT];
__device__ int   d_slot[NSLOT];

__device__ __nv_bfloat16 d_xh[N_TOK * DIM],  d_xl[N_TOK * DIM];
__device__ __nv_bfloat16 d_Wgs_h[DS * DIM],  d_Wgs_l[DS * DIM];   // [N=DS][K=DIM]
__device__ __nv_bfloat16 d_Wus_h[DS * DIM],  d_Wus_l[DS * DIM];
__device__ __nv_bfloat16 d_Wds_h[DIM * DS],  d_Wds_l[DIM * DS];   // [N=DIM][K=DS]
__device__ __nv_bfloat16 d_Wge_h[NE * DE * DIM], d_Wge_l[NE * DE * DIM]; // [e][N=DE][K=DIM]
__device__ __nv_bfloat16 d_Wue_h[NE * DE * DIM], d_Wue_l[NE * DE * DIM];
__device__ __nv_bfloat16 d_Wde_h[NE * DIM * DE], d_Wde_l[NE * DIM * DE]; // [e][N=DIM][K=DE]

__device__ __nv_bfloat16 d_Hs_h[N_TOK * DS], d_Hs_l[N_TOK * DS];
__device__ __nv_bfloat16 d_Hr_h[NSLOT * DE], d_Hr_l[NSLOT * DE];
__device__ float d_R [NSLOT * DIM];

// ----------------- asm helpers (base-target sm_80-class only) -----------------
__device__ __forceinline__ uint32_t sm2u32(const void* p) {
    uint32_t a;
    asm("{ .reg .u64 t; cvta.to.shared.u64 t, %1; cvt.u32.u64 %0, t; }" : "=r"(a) : "l"(p));
    return a;
}
#define SWZ(o) ((o) ^ (((o) >> 3) & 0x70))

#define CPA16(s, g)  asm volatile("cp.async.cg.shared.global [%0], [%1], 16;" :: "r"(s), "l"(g))
#define CPCOMMIT()   asm volatile("cp.async.commit_group;" ::: "memory")
#define CPWAIT1()    asm volatile("cp.async.wait_group 1;" ::: "memory")
#define CPWAIT0()    asm volatile("cp.async.wait_group 0;" ::: "memory")

#define LDMX4(r, a) \
    asm volatile("ldmatrix.sync.aligned.m8n8.x4.shared.b16 {%0,%1,%2,%3}, [%4];" \
        : "=r"((r)[0]), "=r"((r)[1]), "=r"((r)[2]), "=r"((r)[3]) : "r"(a))

#define MMA16816(c, a, b0, b1) \
    asm volatile("mma.sync.aligned.m16n8k16.row.col.f32.bf16.bf16.f32 " \
        "{%0,%1,%2,%3},{%4,%5,%6,%7},{%8,%9},{%0,%1,%2,%3};" \
        : "+f"((c)[0]), "+f"((c)[1]), "+f"((c)[2]), "+f"((c)[3]) \
        : "r"((a)[0]), "r"((a)[1]), "r"((a)[2]), "r"((a)[3]), "r"(b0), "r"(b1))

// ----------------- small kernels -----------------
__global__ void gate_kernel(const float* __restrict__ x, const float* __restrict__ Wg) {
    int n = blockIdx.x;
    __shared__ float xs[DIM];
    __shared__ float logits[NE];
    const float4* xr = (const float4*)(x + (size_t)n * DIM);
    ((float4*)xs)[threadIdx.x] = xr[threadIdx.x];
    __syncthreads();
    int w = threadIdx.x >> 5, l = threadIdx.x & 31;
    float s = 0.f;
    for (int d = l; d < DIM; d += 32) s += xs[d] * Wg[d * NE + w];
    #pragma unroll
    for (int o = 16; o; o >>= 1) s += __shfl_xor_sync(0xffffffffu, s, o);
    if (l == 0) logits[w] = s;
    __syncthreads();
    if (threadIdx.x == 0) {
        float mx = logits[0];
        #pragma unroll
        for (int e = 1; e < NE; e++) mx = fmaxf(mx, logits[e]);
        float p[NE], den = 0.f;
        #pragma unroll
        for (int e = 0; e < NE; e++) { p[e] = expf(logits[e] - mx); den += p[e]; }
        float inv = 1.f / den;
        int i0 = 0;
        #pragma unroll
        for (int e = 1; e < NE; e++) if (p[e] > p[i0]) i0 = e;
        int i1 = (i0 == 0) ? 1 : 0;
        #pragma unroll
        for (int e = 0; e < NE; e++) if (e != i0 && p[e] > p[i1]) i1 = e;
        d_cid[2*n]   = i0; d_cw[2*n]   = p[i0] * inv;
        d_cid[2*n+1] = i1; d_cw[2*n+1] = p[i1] * inv;
    }
}

__global__ void build_kernel() {
    __shared__ int cnt[NE], off[NE], cur[NE];
    if (threadIdx.x < NE) cnt[threadIdx.x] = 0;
    __syncthreads();
    for (int s = threadIdx.x; s < NSLOT; s += 256) atomicAdd(&cnt[d_cid[s]], 1);
    __syncthreads();
    if (threadIdx.x == 0) {
        int a = 0;
        for (int e = 0; e < NE; e++) { off[e] = a; cur[e] = a; a += cnt[e]; d_ecnt[e] = cnt[e]; d_eoff[e] = off[e]; }
    }
    __syncthreads();
    for (int s = threadIdx.x; s < NSLOT; s += 256) {
        int e = d_cid[s];
        int slot = atomicAdd(&cur[e], 1);
        d_etok[slot] = s >> 1;
        d_ewt[slot]  = d_cw[s];
        d_slot[s]    = slot;
    }
}

__device__ __forceinline__ void split2(float v, __nv_bfloat16& h, __nv_bfloat16& l) {
    h = __float2bfloat16(v);
    l = __float2bfloat16(v - __bfloat162float(h));
}

__global__ void convX(const float* __restrict__ x) {
    int i = blockIdx.x * blockDim.x + threadIdx.x;   // one float4 per thread
    float4 v = ((const float4*)x)[i];
    __nv_bfloat16 h0,h1,h2,h3,l0,l1,l2,l3;
    split2(v.x,h0,l0); split2(v.y,h1,l1); split2(v.z,h2,l2); split2(v.w,h3,l3);
    __nv_bfloat162* ph = (__nv_bfloat162*)d_xh;
    __nv_bfloat162* pl = (__nv_bfloat162*)d_xl;
    __nv_bfloat162 a; a.x=h0; a.y=h1; __nv_bfloat162 b; b.x=h2; b.y=h3;
    ph[2*i] = a; ph[2*i+1] = b;
    a.x=l0; a.y=l1; b.x=l2; b.y=l3;
    pl[2*i] = a; pl[2*i+1] = b;
}

// all weight transposes in ONE launch. src [K][N] fp32 -> dst [N][K] bf16 hi/lo.
__global__ void convT_all(const float* __restrict__ Wgs, const float* __restrict__ Wus,
                          const float* __restrict__ Wds, const float* __restrict__ Wge,
                          const float* __restrict__ Wue, const float* __restrict__ Wde) {
    int id = blockIdx.x;
    const float* src; __nv_bfloat16 *dh, *dl; int K, N, tile;
    if (id < 1024)      { src = Wgs; dh = d_Wgs_h; dl = d_Wgs_l; K = DIM; N = DS;  tile = id; }
    else if (id < 2048) { src = Wus; dh = d_Wus_h; dl = d_Wus_l; K = DIM; N = DS;  tile = id - 1024; }
    else if (id < 3072) { src = Wds; dh = d_Wds_h; dl = d_Wds_l; K = DS;  N = DIM; tile = id - 2048; }
    else if (id < 7168) {
        int l = id - 3072; int b = l >> 9; tile = l & 511; K = DIM; N = DE;
        src = Wge + (size_t)b * DIM * DE; dh = d_Wge_h + (size_t)b * DE * DIM; dl = d_Wge_l + (size_t)b * DE * DIM;
    } else if (id < 11264) {
        int l = id - 7168; int b = l >> 9; tile = l & 511; K = DIM; N = DE;
        src = Wue + (size_t)b * DIM * DE; dh = d_Wue_h + (size_t)b * DE * DIM; dl = d_Wue_l + (size_t)b * DE * DIM;
    } else {
        int l = id - 11264; int b = l >> 9; tile = l & 511; K = DE; N = DIM;
        src = Wde + (size_t)b * DE * DIM; dh = d_Wde_h + (size_t)b * DIM * DE; dl = d_Wde_l + (size_t)b * DIM * DE;
    }
    int tilesX = N / 32;
    int n0 = (tile % tilesX) * 32, k0 = (tile / tilesX) * 32;
    __shared__ float t[32][33];
    int tx = threadIdx.x, ty = threadIdx.y;
    #pragma unroll
    for (int i = 0; i < 32; i += 8) t[ty + i][tx] = src[(size_t)(k0 + ty + i) * N + n0 + tx];
    __syncthreads();
    #pragma unroll
    for (int i = 0; i < 32; i += 8) {
        float v = t[tx][ty + i];
        __nv_bfloat16 h, l; split2(v, h, l);
        size_t o = (size_t)(n0 + ty + i) * K + k0 + tx;
        dh[o] = h; dl[o] = l;
    }
}

__device__ __forceinline__ float silu(float g) { return g * (1.f / (1.f + expf(-g))); }

__global__ void combine_kernel(float* __restrict__ out) {
    int n = blockIdx.x;
    int t = threadIdx.x;
    int s0 = d_slot[2 * n], s1 = d_slot[2 * n + 1];
    float4* o4 = (float4*)(out + (size_t)n * DIM);
    const float4* r0 = (const float4*)(d_R + (size_t)s0 * DIM);
    const float4* r1 = (const float4*)(d_R + (size_t)s1 * DIM);
    float4 a = o4[t], b = r0[t], c = r1[t];
    a.x += b.x + c.x; a.y += b.y + c.y; a.z += b.z + c.z; a.w += b.w + c.w;
    o4[t] = a;
}

// ============================================================
// Fused hidden GEMM: H = silu(x@Wg^T) * (x@Wu^T) [* wt], bf16 hi/lo out.
// Tile M=128, N=64 per matrix, K-chunk 64, 256 thr, warp grid 2x4 (warp 64x16).
// z=0: dense shared (x -> Hs); z=1..8: expert e=z-1 gathered (x[tok] -> Hr, *wt)
// ============================================================
#define H_AH  0
#define H_AL  16384
#define H_BGH 32768
#define H_BGL 40960
#define H_BUH 49152
#define H_BUL 57344
#define H_STG 65536
#define H_TOT (2 * H_STG)

__global__ void __launch_bounds__(256) hidden_gemm() {
    extern __shared__ char sm[];
    int tid = threadIdx.x, lane = tid & 31, wid = tid >> 5;
    int wm = wid >> 2, wn = wid & 3;
    int z = blockIdx.z, bx = blockIdx.x;
    int m0 = blockIdx.y * 128;
    bool routed = (z > 0);
    int ldRow = tid >> 1, ldHalf = tid & 1;

    const __nv_bfloat16 *Bgh, *Bgl, *Buh, *Bul;
    __nv_bfloat16 *Hh, *Hl;
    int ldOut, cRowBase, mValid, aRowLd;
    const int K = DIM;

    if (!routed) {
        if (m0 >= N_TOK) return;           // grid.y=32 covers routed worst case
        Bgh = d_Wgs_h; Bgl = d_Wgs_l; Buh = d_Wus_h; Bul = d_Wus_l;
        Hh = d_Hs_h; Hl = d_Hs_l; ldOut = DS;
        mValid = 128; cRowBase = m0; aRowLd = m0 + ldRow;
    } else {
        if (bx >= DE / 64) return;
        int e = z - 1;
        int cnt = d_ecnt[e], off = d_eoff[e];
        if (m0 >= cnt) return;
        size_t wb = (size_t)e * DE * DIM;
        Bgh = d_Wge_h + wb; Bgl = d_Wge_l + wb; Buh = d_Wue_h + wb; Bul = d_Wue_l + wb;
        Hh = d_Hr_h; Hl = d_Hr_l; ldOut = DE;
        mValid = cnt - m0; if (mValid > 128) mValid = 128;
        cRowBase = off + m0;
        int m = m0 + ldRow; if (m > cnt - 1) m = cnt - 1;
        aRowLd = d_etok[off + m];
    }
    int n0 = bx * 64;
    Bgh += (size_t)n0 * K; Bgl += (size_t)n0 * K;
    Buh += (size_t)n0 * K; Bul += (size_t)n0 * K;

    uint32_t sbase = sm2u32(sm);
    const char* aGh = (const char*)(d_xh + (size_t)aRowLd * DIM);
    const char* aGl = (const char*)(d_xl + (size_t)aRowLd * DIM);
    uint32_t soff[4];
    #pragma unroll
    for (int i = 0; i < 4; i++) soff[i] = SWZ((uint32_t)(ldRow * 128 + ldHalf * 64 + i * 16));
    int gOffBase = ldHalf * 64;

    // B: 64 rows x 128B per buf -> 512 16B chunks; thread loads chunks tid, tid+256
    int bI0 = tid, bI1 = tid + 256;
    uint32_t bS0 = SWZ((uint32_t)((bI0 >> 3) * 128 + (bI0 & 7) * 16));
    uint32_t bS1 = SWZ((uint32_t)((bI1 >> 3) * 128 + (bI1 & 7) * 16));
    size_t bG0 = (size_t)(bI0 >> 3) * (K * 2) + (bI0 & 7) * 16;
    size_t bG1 = (size_t)(bI1 >> 3) * (K * 2) + (bI1 & 7) * 16;

    const int nChunks = K / 64;

    // prologue
    {
        uint32_t sb = sbase;
        #pragma unroll
        for (int i = 0; i < 4; i++) {
            size_t g = gOffBase + i * 16;
            CPA16(sb + H_AH + soff[i], aGh + g);
            CPA16(sb + H_AL + soff[i], aGl + g);
        }
        CPA16(sb + H_BGH + bS0, (const char*)Bgh + bG0);
        CPA16(sb + H_BGH + bS1, (const char*)Bgh + bG1);
        CPA16(sb + H_BGL + bS0, (const char*)Bgl + bG0);
        CPA16(sb + H_BGL + bS1, (const char*)Bgl + bG1);
        CPA16(sb + H_BUH + bS0, (const char*)Buh + bG0);
        CPA16(sb + H_BUH + bS1, (const char*)Buh + bG1);
        CPA16(sb + H_BUL + bS0, (const char*)Bul + bG0);
        CPA16(sb + H_BUL + bS1, (const char*)Bul + bG1);
        CPCOMMIT();
    }

    float ag[4][2][4], au[4][2][4];
    #pragma unroll
    for (int a = 0; a < 4; a++)
        #pragma unroll
        for (int b = 0; b < 2; b++)
            #pragma unroll
            for (int cR = 0; cR < 4; cR++) { ag[a][b][cR] = 0.f; au[a][b][cR] = 0.f; }

    int aRowB = wm * 64 + (lane & 15);
    int aColH = (lane >> 4) * 8;
    int bRowB = wn * 16 + (lane & 7) + ((lane >> 4) << 3);
    int bColH = ((lane >> 3) & 1) * 8;

    for (int c = 0; c < nChunks; c++) {
        int st = c & 1;
        if (c + 1 < nChunks) {
            size_t kb = (size_t)(c + 1) * 128;
            uint32_t sb = sbase + (st ^ 1) * H_STG;
            #pragma unroll
            for (int i = 0; i < 4; i++) {
                size_t g = kb + gOffBase + i * 16;
                CPA16(sb + H_AH + soff[i], aGh + g);
                CPA16(sb + H_AL + soff[i], aGl + g);
            }
            CPA16(sb + H_BGH + bS0, (const char*)Bgh + kb + bG0);
            CPA16(sb + H_BGH + bS1, (const char*)Bgh + kb + bG1);
            CPA16(sb + H_BGL + bS0, (const char*)Bgl + kb + bG0);
            CPA16(sb + H_BGL + bS1, (const char*)Bgl + kb + bG1);
            CPA16(sb + H_BUH + bS0, (const char*)Buh + kb + bG0);
            CPA16(sb + H_BUH + bS1, (const char*)Buh + kb + bG1);
            CPA16(sb + H_BUL + bS0, (const char*)Bul + kb + bG0);
            CPA16(sb + H_BUL + bS1, (const char*)Bul + kb + bG1);
            CPCOMMIT();
            CPWAIT1();
        } else {
            CPWAIT0();
        }
        __syncthreads();

        uint32_t sb = sbase + st * H_STG;
        #pragma unroll
        for (int ks = 0; ks < 4; ks++) {
            uint32_t ah[4][4], al[4][4], bgh[4], bgl[4], buh[4], bul[4];
            #pragma unroll
            for (int mt = 0; mt < 4; mt++) {
                uint32_t sw = SWZ((uint32_t)((aRowB + mt * 16) * 128 + (ks * 16 + aColH) * 2));
                LDMX4(ah[mt], sb + H_AH + sw);
                LDMX4(al[mt], sb + H_AL + sw);
            }
            {
                uint32_t sw = SWZ((uint32_t)(bRowB * 128 + (ks * 16 + bColH) * 2));
                LDMX4(bgh, sb + H_BGH + sw);
                LDMX4(bgl, sb + H_BGL + sw);
                LDMX4(buh, sb + H_BUH + sw);
                LDMX4(bul, sb + H_BUL + sw);
            }
            #pragma unroll
            for (int mt = 0; mt < 4; mt++) {
                #pragma unroll
                for (int n8 = 0; n8 < 2; n8++) {
                    int j = n8 * 2;
                    MMA16816(ag[mt][n8], ah[mt], bgh[j], bgh[j + 1]);
                    MMA16816(ag[mt][n8], ah[mt], bgl[j], bgl[j + 1]);
                    MMA16816(ag[mt][n8], al[mt], bgh[j], bgh[j + 1]);
                    MMA16816(au[mt][n8], ah[mt], buh[j], buh[j + 1]);
                    MMA16816(au[mt][n8], ah[mt], bul[j], bul[j + 1]);
                    MMA16816(au[mt][n8], al[mt], buh[j], buh[j + 1]);
                }
            }
        }
        __syncthreads();
    }

    // epilogue: h = silu(g)*u (*wt), split to bf16 hi/lo, store bf16x2 pairs
    #pragma unroll
    for (int mt = 0; mt < 4; mt++) {
        #pragma unroll
        for (int h = 0; h < 2; h++) {
            int rIn = wm * 64 + mt * 16 + (lane >> 2) + h * 8;
            if (rIn < mValid) {
                float wt = routed ? d_ewt[cRowBase + rIn] : 1.0f;
                size_t rowOff = (size_t)(cRowBase + rIn) * ldOut;
                #pragma unroll
                for (int n8 = 0; n8 < 2; n8++) {
                    int col = n0 + wn * 16 + n8 * 8 + (lane & 3) * 2;
                    float v0 = wt * silu(ag[mt][n8][h * 2 + 0]) * au[mt][n8][h * 2 + 0];
                    float v1 = wt * silu(ag[mt][n8][h * 2 + 1]) * au[mt][n8][h * 2 + 1];
                    __nv_bfloat16 h0, l0, h1, l1;
                    split2(v0, h0, l0); split2(v1, h1, l1);
                    __nv_bfloat162 hv; hv.x = h0; hv.y = h1;
                    __nv_bfloat162 lv; lv.x = l0; lv.y = l1;
                    *(__nv_bfloat162*)(Hh + rowOff + col) = hv;
                    *(__nv_bfloat162*)(Hl + rowOff + col) = lv;
                }
            }
        }
    }
}

// ============================================================
// Down GEMM (merged): z=0 dense Hs@Wds -> out; z=1..8 Hr@Wde[e] -> R
// tile 128x128x64, 256 thr, warp grid 2x4 (warp 64x32), 3-term split-bf16
// ============================================================
#define D_AH 0
#define D_AL 16384
#define D_BH 32768
#define D_BL 49152
#define D_STG 65536
#define D_TOT (2 * D_STG)

__global__ void __launch_bounds__(256) down_gemm(float* __restrict__ out) {
    extern __shared__ char sm[];
    int tid = threadIdx.x, lane = tid & 31, wid = tid >> 5;
    int wm = wid >> 2, wn = wid & 3;
    int z = blockIdx.z;
    int m0 = blockIdx.y * 128;
    bool routed = (z > 0);
    int ldRow = tid >> 1, ldHalf = tid & 1;

    const __nv_bfloat16 *Ah, *Al, *Bh, *Bl;
    float* C;
    int K, lda, mValid, cRowBase, aRowLd;

    if (!routed) {
        if (m0 >= N_TOK) return;
        Ah = d_Hs_h; Al = d_Hs_l; lda = DS; K = DS;
        Bh = d_Wds_h; Bl = d_Wds_l;
        C = out;
        mValid = 128; cRowBase = m0; aRowLd = m0 + ldRow;
    } else {
        int e = z - 1;
        int cnt = d_ecnt[e], off = d_eoff[e];
        if (m0 >= cnt) return;
        Ah = d_Hr_h; Al = d_Hr_l; lda = DE; K = DE;
        Bh = d_Wde_h + (size_t)e * DIM * DE; Bl = d_Wde_l + (size_t)e * DIM * DE;
        C = d_R;
        mValid = cnt - m0; if (mValid > 128) mValid = 128;
        cRowBase = off + m0;
        int m = m0 + ldRow; if (m > cnt - 1) m = cnt - 1;
        aRowLd = off + m;
    }
    int n0 = blockIdx.x * 128;
    Bh += (size_t)n0 * K;
    Bl += (size_t)n0 * K;

    uint32_t sbase = sm2u32(sm);
    const char* aGh = (const char*)(Ah + (size_t)aRowLd * lda);
    const char* aGl = (const char*)(Al + (size_t)aRowLd * lda);
    const char* bGh = (const char*)(Bh + (size_t)ldRow * K);
    const char* bGl = (const char*)(Bl + (size_t)ldRow * K);
    uint32_t soff[4];
    #pragma unroll
    for (int i = 0; i < 4; i++) soff[i] = SWZ((uint32_t)(ldRow * 128 + ldHalf * 64 + i * 16));
    int gOffBase = ldHalf * 64;

    int nChunks = K / 64;

    {
        uint32_t sb = sbase;
        #pragma unroll
        for (int i = 0; i < 4; i++) {
            size_t g = gOffBase + i * 16;
            CPA16(sb + D_AH + soff[i], aGh + g);
            CPA16(sb + D_AL + soff[i], aGl + g);
            CPA16(sb + D_BH + soff[i], bGh + g);
            CPA16(sb + D_BL + soff[i], bGl + g);
        }
        CPCOMMIT();
    }

    float acc[4][4][4];
    #pragma unroll
    for (int a = 0; a < 4; a++)
        #pragma unroll
        for (int b = 0; b < 4; b++)
            #pragma unroll
            for (int cR = 0; cR < 4; cR++) acc[a][b][cR] = 0.f;

    int aRowB = wm * 64 + (lane & 15);
    int aColH = (lane >> 4) * 8;
    int bRowB = wn * 32 + (lane & 7) + ((lane >> 4) << 3);
    int bColH = ((lane >> 3) & 1) * 8;

    for (int c = 0; c < nChunks; c++) {
        int st = c & 1;
        if (c + 1 < nChunks) {
            size_t gk = (size_t)(c + 1) * 128 + gOffBase;
            uint32_t sb = sbase + (st ^ 1) * D_STG;
            #pragma unroll
            for (int i = 0; i < 4; i++) {
                size_t g = gk + i * 16;
                CPA16(sb + D_AH + soff[i], aGh + g);
                CPA16(sb + D_AL + soff[i], aGl + g);
                CPA16(sb + D_BH + soff[i], bGh + g);
                CPA16(sb + D_BL + soff[i], bGl + g);
            }
            CPCOMMIT();
            CPWAIT1();
        } else {
            CPWAIT0();
        }
        __syncthreads();

        uint32_t sb = sbase + st * D_STG;
        #pragma unroll
        for (int ks = 0; ks < 4; ks++) {
            uint32_t ah[4][4], al[4][4], bh[2][4], bl[2][4];
            #pragma unroll
            for (int mt = 0; mt < 4; mt++) {
                uint32_t sw = SWZ((uint32_t)((aRowB + mt * 16) * 128 + (ks * 16 + aColH) * 2));
                LDMX4(ah[mt], sb + D_AH + sw);
                LDMX4(al[mt], sb + D_AL + sw);
            }
            #pragma unroll
            for (int g = 0; g < 2; g++) {
                uint32_t sw = SWZ((uint32_t)((bRowB + g * 16) * 128 + (ks * 16 + bColH) * 2));
                LDMX4(bh[g], sb + D_BH + sw);
                LDMX4(bl[g], sb + D_BL + sw);
            }
            #pragma unroll
            for (int mt = 0; mt < 4; mt++) {
                #pragma unroll
                for (int n8 = 0; n8 < 4; n8++) {
                    int g = n8 >> 1, j = (n8 & 1) * 2;
                    MMA16816(acc[mt][n8], ah[mt], bh[g][j], bh[g][j + 1]);
                    MMA16816(acc[mt][n8], ah[mt], bl[g][j], bl[g][j + 1]);
                    MMA16816(acc[mt][n8], al[mt], bh[g][j], bh[g][j + 1]);
                }
            }
        }
        __syncthreads();
    }

    #pragma unroll
    for (int mt = 0; mt < 4; mt++) {
        #pragma unroll
        for (int h = 0; h < 2; h++) {
            int rIn = wm * 64 + mt * 16 + (lane >> 2) + h * 8;
            if (rIn < mValid) {
                float* p = C + (size_t)(cRowBase + rIn) * DIM + n0 + wn * 32 + (lane & 3) * 2;
                #pragma unroll
                for (int n8 = 0; n8 < 4; n8++) {
                    float2 v; v.x = acc[mt][n8][h * 2 + 0]; v.y = acc[mt][n8][h * 2 + 1];
                    *(float2*)(p + n8 * 8) = v;
                }
            }
        }
    }
}

// ----------------- launch -----------------
extern "C" void kernel_launch(void* const* d_in, const int* in_sizes, int n_in,
                              void* d_out, int out_size) {
    const float* x   = (const float*)d_in[0];
    const float* Wg  = (const float*)d_in[1];
    const float* Wge = (const float*)d_in[2];
    const float* Wue = (const float*)d_in[3];
    const float* Wde = (const float*)d_in[4];
    const float* Wgs = (const float*)d_in[5];
    const float* Wus = (const float*)d_in[6];
    const float* Wds = (const float*)d_in[7];
    float* out = (float*)d_out;

    cudaFuncSetAttribute(hidden_gemm, cudaFuncAttributeMaxDynamicSharedMemorySize, H_TOT);
    cudaFuncSetAttribute(down_gemm,   cudaFuncAttributeMaxDynamicSharedMemorySize, D_TOT);

    convX<<<N_TOK * DIM / 4 / 256, 256>>>(x);                            // 1
    convT_all<<<15360, dim3(32, 8)>>>(Wgs, Wus, Wds, Wge, Wue, Wde);     // 2
    gate_kernel<<<N_TOK, 256>>>(x, Wg);                                  // 3
    build_kernel<<<1, 256>>>();                                          // 4
    hidden_gemm<<<dim3(16, 32, 9), 256, H_TOT>>>();                      // 5
    down_gemm<<<dim3(8, 32, 9), 256, D_TOT>>>(out);                      // 6  <- ncu captures this
    combine_kernel<<<N_TOK, 256>>>(out);                                 // 7
}

// round 5
// speedup vs baseline: 2.6296x; 1.0461x over previous
#include <cuda_runtime.h>
#include <cuda_bf16.h>
#include <math.h>
#include <stdint.h>

#define N_TOK 2048
#define DIM   1024
#define DE    512
#define DS    1024
#define NE    8
#define NSLOT (N_TOK * 2)
#define ECAP  2048              // max tokens per expert (top-2, distinct experts)

// ----------------- scratch (device globals; no allocs) -----------------
__device__ int   d_ecnt[NE];                 // zeroed via cudaMemsetAsync each call
__device__ int   d_etok[NE * ECAP];
__device__ float d_ewt [NE * ECAP];
__device__ int   d_slot[NSLOT];

__device__ __nv_bfloat16 d_xh[N_TOK * DIM],  d_xl[N_TOK * DIM];
__device__ __nv_bfloat16 d_Wgs_h[DS * DIM],  d_Wgs_l[DS * DIM];   // [N=DS][K=DIM]
__device__ __nv_bfloat16 d_Wus_h[DS * DIM],  d_Wus_l[DS * DIM];
__device__ __nv_bfloat16 d_Wds_h[DIM * DS],  d_Wds_l[DIM * DS];   // [N=DIM][K=DS]
__device__ __nv_bfloat16 d_Wge_h[NE * DE * DIM], d_Wge_l[NE * DE * DIM]; // [e][N=DE][K=DIM]
__device__ __nv_bfloat16 d_Wue_h[NE * DE * DIM], d_Wue_l[NE * DE * DIM];
__device__ __nv_bfloat16 d_Wde_h[NE * DIM * DE], d_Wde_l[NE * DIM * DE]; // [e][N=DIM][K=DE]

__device__ __nv_bfloat16 d_Hs_h[N_TOK * DS], d_Hs_l[N_TOK * DS];
__device__ __nv_bfloat16 d_Hr_h[NE * ECAP * DE], d_Hr_l[NE * ECAP * DE];
__device__ float d_R [NE * ECAP * DIM];

// ----------------- asm helpers (base-target sm_80-class only) -----------------
__device__ __forceinline__ uint32_t sm2u32(const void* p) {
    uint32_t a;
    asm("{ .reg .u64 t; cvta.to.shared.u64 t, %1; cvt.u32.u64 %0, t; }" : "=r"(a) : "l"(p));
    return a;
}
#define SWZ(o) ((o) ^ (((o) >> 3) & 0x70))

#define CPA16(s, g)  asm volatile("cp.async.cg.shared.global [%0], [%1], 16;" :: "r"(s), "l"(g))
#define CPCOMMIT()   asm volatile("cp.async.commit_group;" ::: "memory")
#define CPWAIT1()    asm volatile("cp.async.wait_group 1;" ::: "memory")
#define CPWAIT0()    asm volatile("cp.async.wait_group 0;" ::: "memory")

#define LDMX4(r, a) \
    asm volatile("ldmatrix.sync.aligned.m8n8.x4.shared.b16 {%0,%1,%2,%3}, [%4];" \
        : "=r"((r)[0]), "=r"((r)[1]), "=r"((r)[2]), "=r"((r)[3]) : "r"(a))

#define MMA16816(c, a, b0, b1) \
    asm volatile("mma.sync.aligned.m16n8k16.row.col.f32.bf16.bf16.f32 " \
        "{%0,%1,%2,%3},{%4,%5,%6,%7},{%8,%9},{%0,%1,%2,%3};" \
        : "+f"((c)[0]), "+f"((c)[1]), "+f"((c)[2]), "+f"((c)[3]) \
        : "r"((a)[0]), "r"((a)[1]), "r"((a)[2]), "r"((a)[3]), "r"(b0), "r"(b1))

__device__ __forceinline__ void split2(float v, __nv_bfloat16& h, __nv_bfloat16& l) {
    h = __float2bfloat16(v);
    l = __float2bfloat16(v - __bfloat162float(h));
}

// ----------------- gate + convX + expert routing (fused) -----------------
__global__ void gate_kernel(const float* __restrict__ x, const float* __restrict__ Wg) {
    int n = blockIdx.x;
    int t = threadIdx.x;
    __shared__ float xs[DIM];
    __shared__ float logits[NE];
    float4 v = ((const float4*)(x + (size_t)n * DIM))[t];
    ((float4*)xs)[t] = v;
    // convX: split this token's row to bf16 hi/lo
    {
        __nv_bfloat16 h0,h1,h2,h3,l0,l1,l2,l3;
        split2(v.x,h0,l0); split2(v.y,h1,l1); split2(v.z,h2,l2); split2(v.w,h3,l3);
        size_t o = (size_t)n * DIM + t * 4;
        __nv_bfloat162 a; a.x=h0; a.y=h1; __nv_bfloat162 b; b.x=h2; b.y=h3;
        *(__nv_bfloat162*)(d_xh + o)     = a;
        *(__nv_bfloat162*)(d_xh + o + 2) = b;
        a.x=l0; a.y=l1; b.x=l2; b.y=l3;
        *(__nv_bfloat162*)(d_xl + o)     = a;
        *(__nv_bfloat162*)(d_xl + o + 2) = b;
    }
    __syncthreads();
    int w = t >> 5, l = t & 31;
    float s = 0.f;
    for (int d = l; d < DIM; d += 32) s += xs[d] * Wg[d * NE + w];
    #pragma unroll
    for (int o = 16; o; o >>= 1) s += __shfl_xor_sync(0xffffffffu, s, o);
    if (l == 0) logits[w] = s;
    __syncthreads();
    if (t == 0) {
        float mx = logits[0];
        #pragma unroll
        for (int e = 1; e < NE; e++) mx = fmaxf(mx, logits[e]);
        float p[NE], den = 0.f;
        #pragma unroll
        for (int e = 0; e < NE; e++) { p[e] = expf(logits[e] - mx); den += p[e]; }
        float inv = 1.f / den;
        int i0 = 0;
        #pragma unroll
        for (int e = 1; e < NE; e++) if (p[e] > p[i0]) i0 = e;
        int i1 = (i0 == 0) ? 1 : 0;
        #pragma unroll
        for (int e = 0; e < NE; e++) if (e != i0 && p[e] > p[i1]) i1 = e;
        int p0 = atomicAdd(&d_ecnt[i0], 1);
        int s0 = i0 * ECAP + p0;
        d_etok[s0] = n; d_ewt[s0] = p[i0] * inv; d_slot[2*n] = s0;
        int p1 = atomicAdd(&d_ecnt[i1], 1);
        int s1 = i1 * ECAP + p1;
        d_etok[s1] = n; d_ewt[s1] = p[i1] * inv; d_slot[2*n+1] = s1;
    }
}

// all weight transposes in ONE launch. src [K][N] fp32 -> dst [N][K] bf16 hi/lo.
__global__ void convT_all(const float* __restrict__ Wgs, const float* __restrict__ Wus,
                          const float* __restrict__ Wds, const float* __restrict__ Wge,
                          const float* __restrict__ Wue, const float* __restrict__ Wde) {
    int id = blockIdx.x;
    const float* src; __nv_bfloat16 *dh, *dl; int K, N, tile;
    if (id < 1024)      { src = Wgs; dh = d_Wgs_h; dl = d_Wgs_l; K = DIM; N = DS;  tile = id; }
    else if (id < 2048) { src = Wus; dh = d_Wus_h; dl = d_Wus_l; K = DIM; N = DS;  tile = id - 1024; }
    else if (id < 3072) { src = Wds; dh = d_Wds_h; dl = d_Wds_l; K = DS;  N = DIM; tile = id - 2048; }
    else if (id < 7168) {
        int l = id - 3072; int b = l >> 9; tile = l & 511; K = DIM; N = DE;
        src = Wge + (size_t)b * DIM * DE; dh = d_Wge_h + (size_t)b * DE * DIM; dl = d_Wge_l + (size_t)b * DE * DIM;
    } else if (id < 11264) {
        int l = id - 7168; int b = l >> 9; tile = l & 511; K = DIM; N = DE;
        src = Wue + (size_t)b * DIM * DE; dh = d_Wue_h + (size_t)b * DE * DIM; dl = d_Wue_l + (size_t)b * DE * DIM;
    } else {
        int l = id - 11264; int b = l >> 9; tile = l & 511; K = DE; N = DIM;
        src = Wde + (size_t)b * DE * DIM; dh = d_Wde_h + (size_t)b * DIM * DE; dl = d_Wde_l + (size_t)b * DIM * DE;
    }
    int tilesX = N / 32;
    int n0 = (tile % tilesX) * 32, k0 = (tile / tilesX) * 32;
    __shared__ float t[32][33];
    int tx = threadIdx.x, ty = threadIdx.y;
    #pragma unroll
    for (int i = 0; i < 32; i += 8) t[ty + i][tx] = src[(size_t)(k0 + ty + i) * N + n0 + tx];
    __syncthreads();
    #pragma unroll
    for (int i = 0; i < 32; i += 8) {
        float v = t[tx][ty + i];
        __nv_bfloat16 h, l; split2(v, h, l);
        size_t o = (size_t)(n0 + ty + i) * K + k0 + tx;
        dh[o] = h; dl[o] = l;
    }
}

__device__ __forceinline__ float silu(float g) { return g * (1.f / (1.f + expf(-g))); }

__global__ void combine_kernel(float* __restrict__ out) {
    int n = blockIdx.x;
    int t = threadIdx.x;
    int s0 = d_slot[2 * n], s1 = d_slot[2 * n + 1];
    float4* o4 = (float4*)(out + (size_t)n * DIM);
    const float4* r0 = (const float4*)(d_R + (size_t)s0 * DIM);
    const float4* r1 = (const float4*)(d_R + (size_t)s1 * DIM);
    float4 a = o4[t], b = r0[t], c = r1[t];
    a.x += b.x + c.x; a.y += b.y + c.y; a.z += b.z + c.z; a.w += b.w + c.w;
    o4[t] = a;
}

// ============================================================
// Fused hidden GEMM: H = silu(x@Wg^T) * (x@Wu^T) [* wt], bf16 hi/lo out.
// Tile M=128, N=64 per matrix, K-chunk 64, 256 thr, warp grid 2x4 (warp 64x16).
// z=0: dense shared (x -> Hs); z=1..8: expert e=z-1 gathered (x[tok] -> Hr, *wt)
// ============================================================
#define H_AH  0
#define H_AL  16384
#define H_BGH 32768
#define H_BGL 40960
#define H_BUH 49152
#define H_BUL 57344
#define H_STG 65536
#define H_TOT (2 * H_STG)

__global__ void __launch_bounds__(256) hidden_gemm() {
    extern __shared__ char sm[];
    int tid = threadIdx.x, lane = tid & 31, wid = tid >> 5;
    int wm = wid >> 2, wn = wid & 3;
    int z = blockIdx.z, bx = blockIdx.x;
    int m0 = blockIdx.y * 128;
    bool routed = (z > 0);
    int ldRow = tid >> 1, ldHalf = tid & 1;

    const __nv_bfloat16 *Bgh, *Bgl, *Buh, *Bul;
    __nv_bfloat16 *Hh, *Hl;
    int ldOut, cRowBase, mValid, aRowLd;
    const int K = DIM;

    if (!routed) {
        Bgh = d_Wgs_h; Bgl = d_Wgs_l; Buh = d_Wus_h; Bul = d_Wus_l;
        Hh = d_Hs_h; Hl = d_Hs_l; ldOut = DS;
        mValid = 128; cRowBase = m0; aRowLd = m0 + ldRow;
    } else {
        if (bx >= DE / 64) return;
        int e = z - 1;
        int cnt = d_ecnt[e], off = e * ECAP;
        if (m0 >= cnt) return;
        size_t wb = (size_t)e * DE * DIM;
        Bgh = d_Wge_h + wb; Bgl = d_Wge_l + wb; Buh = d_Wue_h + wb; Bul = d_Wue_l + wb;
        Hh = d_Hr_h; Hl = d_Hr_l; ldOut = DE;
        mValid = cnt - m0; if (mValid > 128) mValid = 128;
        cRowBase = off + m0;
        int m = m0 + ldRow; if (m > cnt - 1) m = cnt - 1;
        aRowLd = d_etok[off + m];
    }
    int n0 = bx * 64;
    Bgh += (size_t)n0 * K; Bgl += (size_t)n0 * K;
    Buh += (size_t)n0 * K; Bul += (size_t)n0 * K;

    uint32_t sbase = sm2u32(sm);
    const char* aGh = (const char*)(d_xh + (size_t)aRowLd * DIM);
    const char* aGl = (const char*)(d_xl + (size_t)aRowLd * DIM);
    uint32_t soff[4];
    #pragma unroll
    for (int i = 0; i < 4; i++) soff[i] = SWZ((uint32_t)(ldRow * 128 + ldHalf * 64 + i * 16));
    int gOffBase = ldHalf * 64;

    int bI0 = tid, bI1 = tid + 256;
    uint32_t bS0 = SWZ((uint32_t)((bI0 >> 3) * 128 + (bI0 & 7) * 16));
    uint32_t bS1 = SWZ((uint32_t)((bI1 >> 3) * 128 + (bI1 & 7) * 16));
    size_t bG0 = (size_t)(bI0 >> 3) * (K * 2) + (bI0 & 7) * 16;
    size_t bG1 = (size_t)(bI1 >> 3) * (K * 2) + (bI1 & 7) * 16;

    const int nChunks = K / 64;

    {
        uint32_t sb = sbase;
        #pragma unroll
        for (int i = 0; i < 4; i++) {
            size_t g = gOffBase + i * 16;
            CPA16(sb + H_AH + soff[i], aGh + g);
            CPA16(sb + H_AL + soff[i], aGl + g);
        }
        CPA16(sb + H_BGH + bS0, (const char*)Bgh + bG0);
        CPA16(sb + H_BGH + bS1, (const char*)Bgh + bG1);
        CPA16(sb + H_BGL + bS0, (const char*)Bgl + bG0);
        CPA16(sb + H_BGL + bS1, (const char*)Bgl + bG1);
        CPA16(sb + H_BUH + bS0, (const char*)Buh + bG0);
        CPA16(sb + H_BUH + bS1, (const char*)Buh + bG1);
        CPA16(sb + H_BUL + bS0, (const char*)Bul + bG0);
        CPA16(sb + H_BUL + bS1, (const char*)Bul + bG1);
        CPCOMMIT();
    }

    float ag[4][2][4], au[4][2][4];
    #pragma unroll
    for (int a = 0; a < 4; a++)
        #pragma unroll
        for (int b = 0; b < 2; b++)
            #pragma unroll
            for (int cR = 0; cR < 4; cR++) { ag[a][b][cR] = 0.f; au[a][b][cR] = 0.f; }

    int aRowB = wm * 64 + (lane & 15);
    int aColH = (lane >> 4) * 8;
    int bRowB = wn * 16 + (lane & 7) + ((lane >> 4) << 3);
    int bColH = ((lane >> 3) & 1) * 8;

    for (int c = 0; c < nChunks; c++) {
        int st = c & 1;
        if (c + 1 < nChunks) {
            size_t kb = (size_t)(c + 1) * 128;
            uint32_t sb = sbase + (st ^ 1) * H_STG;
            #pragma unroll
            for (int i = 0; i < 4; i++) {
                size_t g = kb + gOffBase + i * 16;
                CPA16(sb + H_AH + soff[i], aGh + g);
                CPA16(sb + H_AL + soff[i], aGl + g);
            }
            CPA16(sb + H_BGH + bS0, (const char*)Bgh + kb + bG0);
            CPA16(sb + H_BGH + bS1, (const char*)Bgh + kb + bG1);
            CPA16(sb + H_BGL + bS0, (const char*)Bgl + kb + bG0);
            CPA16(sb + H_BGL + bS1, (const char*)Bgl + kb + bG1);
            CPA16(sb + H_BUH + bS0, (const char*)Buh + kb + bG0);
            CPA16(sb + H_BUH + bS1, (const char*)Buh + kb + bG1);
            CPA16(sb + H_BUL + bS0, (const char*)Bul + kb + bG0);
            CPA16(sb + H_BUL + bS1, (const char*)Bul + kb + bG1);
            CPCOMMIT();
            CPWAIT1();
        } else {
            CPWAIT0();
        }
        __syncthreads();

        uint32_t sb = sbase + st * H_STG;
        #pragma unroll
        for (int ks = 0; ks < 4; ks++) {
            uint32_t ah[4][4], al[4][4], bgh[4], bgl[4], buh[4], bul[4];
            #pragma unroll
            for (int mt = 0; mt < 4; mt++) {
                uint32_t sw = SWZ((uint32_t)((aRowB + mt * 16) * 128 + (ks * 16 + aColH) * 2));
                LDMX4(ah[mt], sb + H_AH + sw);
                LDMX4(al[mt], sb + H_AL + sw);
            }
            {
                uint32_t sw = SWZ((uint32_t)(bRowB * 128 + (ks * 16 + bColH) * 2));
                LDMX4(bgh, sb + H_BGH + sw);
                LDMX4(bgl, sb + H_BGL + sw);
                LDMX4(buh, sb + H_BUH + sw);
                LDMX4(bul, sb + H_BUL + sw);
            }
            #pragma unroll
            for (int mt = 0; mt < 4; mt++) {
                #pragma unroll
                for (int n8 = 0; n8 < 2; n8++) {
                    int j = n8 * 2;
                    MMA16816(ag[mt][n8], ah[mt], bgh[j], bgh[j + 1]);
                    MMA16816(ag[mt][n8], ah[mt], bgl[j], bgl[j + 1]);
                    MMA16816(ag[mt][n8], al[mt], bgh[j], bgh[j + 1]);
                    MMA16816(au[mt][n8], ah[mt], buh[j], buh[j + 1]);
                    MMA16816(au[mt][n8], ah[mt], bul[j], bul[j + 1]);
                    MMA16816(au[mt][n8], al[mt], buh[j], buh[j + 1]);
                }
            }
        }
        __syncthreads();
    }

    #pragma unroll
    for (int mt = 0; mt < 4; mt++) {
        #pragma unroll
        for (int h = 0; h < 2; h++) {
            int rIn = wm * 64 + mt * 16 + (lane >> 2) + h * 8;
            if (rIn < mValid) {
                float wt = routed ? d_ewt[cRowBase + rIn] : 1.0f;
                size_t rowOff = (size_t)(cRowBase + rIn) * ldOut;
                #pragma unroll
                for (int n8 = 0; n8 < 2; n8++) {
                    int col = n0 + wn * 16 + n8 * 8 + (lane & 3) * 2;
                    float v0 = wt * silu(ag[mt][n8][h * 2 + 0]) * au[mt][n8][h * 2 + 0];
                    float v1 = wt * silu(ag[mt][n8][h * 2 + 1]) * au[mt][n8][h * 2 + 1];
                    __nv_bfloat16 h0, l0, h1, l1;
                    split2(v0, h0, l0); split2(v1, h1, l1);
                    __nv_bfloat162 hv; hv.x = h0; hv.y = h1;
                    __nv_bfloat162 lv; lv.x = l0; lv.y = l1;
                    *(__nv_bfloat162*)(Hh + rowOff + col) = hv;
                    *(__nv_bfloat162*)(Hl + rowOff + col) = lv;
                }
            }
        }
    }
}

// ============================================================
// Down GEMM (merged): z=0 dense Hs@Wds -> out; z=1..8 Hr@Wde[e] -> R
// tile 128x128x64, 256 thr, warp grid 2x4 (warp 64x32), 3-term split-bf16
// ============================================================
#define D_AH 0
#define D_AL 16384
#define D_BH 32768
#define D_BL 49152
#define D_STG 65536
#define D_TOT (2 * D_STG)

__global__ void __launch_bounds__(256) down_gemm(float* __restrict__ out) {
    extern __shared__ char sm[];
    int tid = threadIdx.x, lane = tid & 31, wid = tid >> 5;
    int wm = wid >> 2, wn = wid & 3;
    int z = blockIdx.z;
    int m0 = blockIdx.y * 128;
    bool routed = (z > 0);
    int ldRow = tid >> 1, ldHalf = tid & 1;

    const __nv_bfloat16 *Ah, *Al, *Bh, *Bl;
    float* C;
    int K, lda, mValid, cRowBase, aRowLd;

    if (!routed) {
        Ah = d_Hs_h; Al = d_Hs_l; lda = DS; K = DS;
        Bh = d_Wds_h; Bl = d_Wds_l;
        C = out;
        mValid = 128; cRowBase = m0; aRowLd = m0 + ldRow;
    } else {
        int e = z - 1;
        int cnt = d_ecnt[e], off = e * ECAP;
        if (m0 >= cnt) return;
        Ah = d_Hr_h; Al = d_Hr_l; lda = DE; K = DE;
        Bh = d_Wde_h + (size_t)e * DIM * DE; Bl = d_Wde_l + (size_t)e * DIM * DE;
        C = d_R;
        mValid = cnt - m0; if (mValid > 128) mValid = 128;
        cRowBase = off + m0;
        int m = m0 + ldRow; if (m > cnt - 1) m = cnt - 1;
        aRowLd = off + m;
    }
    int n0 = blockIdx.x * 128;
    Bh += (size_t)n0 * K;
    Bl += (size_t)n0 * K;

    uint32_t sbase = sm2u32(sm);
    const char* aGh = (const char*)(Ah + (size_t)aRowLd * lda);
    const char* aGl = (const char*)(Al + (size_t)aRowLd * lda);
    const char* bGh = (const char*)(Bh + (size_t)ldRow * K);
    const char* bGl = (const char*)(Bl + (size_t)ldRow * K);
    uint32_t soff[4];
    #pragma unroll
    for (int i = 0; i < 4; i++) soff[i] = SWZ((uint32_t)(ldRow * 128 + ldHalf * 64 + i * 16));
    int gOffBase = ldHalf * 64;

    int nChunks = K / 64;

    {
        uint32_t sb = sbase;
        #pragma unroll
        for (int i = 0; i < 4; i++) {
            size_t g = gOffBase + i * 16;
            CPA16(sb + D_AH + soff[i], aGh + g);
            CPA16(sb + D_AL + soff[i], aGl + g);
            CPA16(sb + D_BH + soff[i], bGh + g);
            CPA16(sb + D_BL + soff[i], bGl + g);
        }
        CPCOMMIT();
    }

    float acc[4][4][4];
    #pragma unroll
    for (int a = 0; a < 4; a++)
        #pragma unroll
        for (int b = 0; b < 4; b++)
            #pragma unroll
            for (int cR = 0; cR < 4; cR++) acc[a][b][cR] = 0.f;

    int aRowB = wm * 64 + (lane & 15);
    int aColH = (lane >> 4) * 8;
    int bRowB = wn * 32 + (lane & 7) + ((lane >> 4) << 3);
    int bColH = ((lane >> 3) & 1) * 8;

    for (int c = 0; c < nChunks; c++) {
        int st = c & 1;
        if (c + 1 < nChunks) {
            size_t gk = (size_t)(c + 1) * 128 + gOffBase;
            uint32_t sb = sbase + (st ^ 1) * D_STG;
            #pragma unroll
            for (int i = 0; i < 4; i++) {
                size_t g = gk + i * 16;
                CPA16(sb + D_AH + soff[i], aGh + g);
                CPA16(sb + D_AL + soff[i], aGl + g);
                CPA16(sb + D_BH + soff[i], bGh + g);
                CPA16(sb + D_BL + soff[i], bGl + g);
            }
            CPCOMMIT();
            CPWAIT1();
        } else {
            CPWAIT0();
        }
        __syncthreads();

        uint32_t sb = sbase + st * D_STG;
        #pragma unroll
        for (int ks = 0; ks < 4; ks++) {
            uint32_t ah[4][4], al[4][4], bh[2][4], bl[2][4];
            #pragma unroll
            for (int mt = 0; mt < 4; mt++) {
                uint32_t sw = SWZ((uint32_t)((aRowB + mt * 16) * 128 + (ks * 16 + aColH) * 2));
                LDMX4(ah[mt], sb + D_AH + sw);
                LDMX4(al[mt], sb + D_AL + sw);
            }
            #pragma unroll
            for (int g = 0; g < 2; g++) {
                uint32_t sw = SWZ((uint32_t)((bRowB + g * 16) * 128 + (ks * 16 + bColH) * 2));
                LDMX4(bh[g], sb + D_BH + sw);
                LDMX4(bl[g], sb + D_BL + sw);
            }
            #pragma unroll
            for (int mt = 0; mt < 4; mt++) {
                #pragma unroll
                for (int n8 = 0; n8 < 4; n8++) {
                    int g = n8 >> 1, j = (n8 & 1) * 2;
                    MMA16816(acc[mt][n8], ah[mt], bh[g][j], bh[g][j + 1]);
                    MMA16816(acc[mt][n8], ah[mt], bl[g][j], bl[g][j + 1]);
                    MMA16816(acc[mt][n8], al[mt], bh[g][j], bh[g][j + 1]);
                }
            }
        }
        __syncthreads();
    }

    #pragma unroll
    for (int mt = 0; mt < 4; mt++) {
        #pragma unroll
        for (int h = 0; h < 2; h++) {
            int rIn = wm * 64 + mt * 16 + (lane >> 2) + h * 8;
            if (rIn < mValid) {
                float* p = C + (size_t)(cRowBase + rIn) * DIM + n0 + wn * 32 + (lane & 3) * 2;
                #pragma unroll
                for (int n8 = 0; n8 < 4; n8++) {
                    float2 v; v.x = acc[mt][n8][h * 2 + 0]; v.y = acc[mt][n8][h * 2 + 1];
                    *(float2*)(p + n8 * 8) = v;
                }
            }
        }
    }
}

// ----------------- launch -----------------
extern "C" void kernel_launch(void* const* d_in, const int* in_sizes, int n_in,
                              void* d_out, int out_size) {
    const float* x   = (const float*)d_in[0];
    const float* Wg  = (const float*)d_in[1];
    const float* Wge = (const float*)d_in[2];
    const float* Wue = (const float*)d_in[3];
    const float* Wde = (const float*)d_in[4];
    const float* Wgs = (const float*)d_in[5];
    const float* Wus = (const float*)d_in[6];
    const float* Wds = (const float*)d_in[7];
    float* out = (float*)d_out;

    cudaFuncSetAttribute(hidden_gemm, cudaFuncAttributeMaxDynamicSharedMemorySize, H_TOT);
    cudaFuncSetAttribute(down_gemm,   cudaFuncAttributeMaxDynamicSharedMemorySize, D_TOT);

    void* ecnt_ptr;
    cudaGetSymbolAddress(&ecnt_ptr, d_ecnt);
    cudaMemsetAsync(ecnt_ptr, 0, NE * sizeof(int), 0);

    convT_all<<<15360, dim3(32, 8)>>>(Wgs, Wus, Wds, Wge, Wue, Wde);     // 1
    gate_kernel<<<N_TOK, 256>>>(x, Wg);                                  // 2 (gating + convX + routing)
    hidden_gemm<<<dim3(16, 16, 9), 256, H_TOT>>>();                      // 3
    down_gemm<<<dim3(8, 16, 9), 256, D_TOT>>>(out);                      // 4  <- profiled
    combine_kernel<<<N_TOK, 256>>>(out);                                 // 5
}

// round 6
// speedup vs baseline: 2.9449x; 1.1199x over previous
#include <cuda_runtime.h>
#include <cuda_bf16.h>
#include <math.h>
#include <stdint.h>

#define N_TOK 2048
#define DIM   1024
#define DE    512
#define DS    1024
#define NE    8
#define NSLOT (N_TOK * 2)
#define ECAP  2048

// ----------------- scratch (device globals; no allocs) -----------------
__device__ int   d_ecnt[NE];                 // zeroed via cudaMemsetAsync
__device__ int   d_etok[NE * ECAP];
__device__ float d_ewt [NE * ECAP];
__device__ int   d_slot[NSLOT];

__device__ __nv_bfloat16 d_xh[N_TOK * DIM],  d_xl[N_TOK * DIM];
__device__ __nv_bfloat16 d_Wgs_h[DS * DIM],  d_Wgs_l[DS * DIM];
__device__ __nv_bfloat16 d_Wus_h[DS * DIM],  d_Wus_l[DS * DIM];
__device__ __nv_bfloat16 d_Wds_h[DIM * DS],  d_Wds_l[DIM * DS];
__device__ __nv_bfloat16 d_Wge_h[NE * DE * DIM], d_Wge_l[NE * DE * DIM];
__device__ __nv_bfloat16 d_Wue_h[NE * DE * DIM], d_Wue_l[NE * DE * DIM];
__device__ __nv_bfloat16 d_Wde_h[NE * DIM * DE], d_Wde_l[NE * DIM * DE];

__device__ __nv_bfloat16 d_Hs_h[N_TOK * DS], d_Hs_l[N_TOK * DS];
__device__ __nv_bfloat16 d_Hr_h[NE * ECAP * DE], d_Hr_l[NE * ECAP * DE];
__device__ float d_R [NE * ECAP * DIM];

// ----------------- asm helpers -----------------
__device__ __forceinline__ uint32_t sm2u32(const void* p) {
    uint32_t a;
    asm("{ .reg .u64 t; cvta.to.shared.u64 t, %1; cvt.u32.u64 %0, t; }" : "=r"(a) : "l"(p));
    return a;
}
#define SWZ(o) ((o) ^ (((o) >> 3) & 0x70))

#define CPA16(s, g)  asm volatile("cp.async.cg.shared.global [%0], [%1], 16;" :: "r"(s), "l"(g))
#define CPCOMMIT()   asm volatile("cp.async.commit_group;" ::: "memory")
#define CPWAIT2()    asm volatile("cp.async.wait_group 2;" ::: "memory")
#define CPWAIT1()    asm volatile("cp.async.wait_group 1;" ::: "memory")
#define CPWAIT0()    asm volatile("cp.async.wait_group 0;" ::: "memory")

#define LDMX4(r, a) \
    asm volatile("ldmatrix.sync.aligned.m8n8.x4.shared.b16 {%0,%1,%2,%3}, [%4];" \
        : "=r"((r)[0]), "=r"((r)[1]), "=r"((r)[2]), "=r"((r)[3]) : "r"(a))

#define MMA16816(c, a, b0, b1) \
    asm volatile("mma.sync.aligned.m16n8k16.row.col.f32.bf16.bf16.f32 " \
        "{%0,%1,%2,%3},{%4,%5,%6,%7},{%8,%9},{%0,%1,%2,%3};" \
        : "+f"((c)[0]), "+f"((c)[1]), "+f"((c)[2]), "+f"((c)[3]) \
        : "r"((a)[0]), "r"((a)[1]), "r"((a)[2]), "r"((a)[3]), "r"(b0), "r"(b1))

__device__ __forceinline__ void split2(float v, __nv_bfloat16& h, __nv_bfloat16& l) {
    h = __float2bfloat16(v);
    l = __float2bfloat16(v - __bfloat162float(h));
}

// ----------------- gate + convX + routing (fused) -----------------
__global__ void gate_kernel(const float* __restrict__ x, const float* __restrict__ Wg) {
    int n = blockIdx.x;
    int t = threadIdx.x;
    __shared__ float xs[DIM];
    __shared__ float logits[NE];
    float4 v = ((const float4*)(x + (size_t)n * DIM))[t];
    ((float4*)xs)[t] = v;
    {
        __nv_bfloat16 h0,h1,h2,h3,l0,l1,l2,l3;
        split2(v.x,h0,l0); split2(v.y,h1,l1); split2(v.z,h2,l2); split2(v.w,h3,l3);
        size_t o = (size_t)n * DIM + t * 4;
        __nv_bfloat162 a; a.x=h0; a.y=h1; __nv_bfloat162 b; b.x=h2; b.y=h3;
        *(__nv_bfloat162*)(d_xh + o)     = a;
        *(__nv_bfloat162*)(d_xh + o + 2) = b;
        a.x=l0; a.y=l1; b.x=l2; b.y=l3;
        *(__nv_bfloat162*)(d_xl + o)     = a;
        *(__nv_bfloat162*)(d_xl + o + 2) = b;
    }
    __syncthreads();
    int w = t >> 5, l = t & 31;
    float s = 0.f;
    for (int d = l; d < DIM; d += 32) s += xs[d] * Wg[d * NE + w];
    #pragma unroll
    for (int o = 16; o; o >>= 1) s += __shfl_xor_sync(0xffffffffu, s, o);
    if (l == 0) logits[w] = s;
    __syncthreads();
    if (t == 0) {
        float mx = logits[0];
        #pragma unroll
        for (int e = 1; e < NE; e++) mx = fmaxf(mx, logits[e]);
        float p[NE], den = 0.f;
        #pragma unroll
        for (int e = 0; e < NE; e++) { p[e] = expf(logits[e] - mx); den += p[e]; }
        float inv = 1.f / den;
        int i0 = 0;
        #pragma unroll
        for (int e = 1; e < NE; e++) if (p[e] > p[i0]) i0 = e;
        int i1 = (i0 == 0) ? 1 : 0;
        #pragma unroll
        for (int e = 0; e < NE; e++) if (e != i0 && p[e] > p[i1]) i1 = e;
        int p0 = atomicAdd(&d_ecnt[i0], 1);
        int s0 = i0 * ECAP + p0;
        d_etok[s0] = n; d_ewt[s0] = p[i0] * inv; d_slot[2*n] = s0;
        int p1 = atomicAdd(&d_ecnt[i1], 1);
        int s1 = i1 * ECAP + p1;
        d_etok[s1] = n; d_ewt[s1] = p[i1] * inv; d_slot[2*n+1] = s1;
    }
}

// weight transposes, one launch: src [K][N] fp32 -> [N][K] bf16 hi/lo
__global__ void convT_all(const float* __restrict__ Wgs, const float* __restrict__ Wus,
                          const float* __restrict__ Wds, const float* __restrict__ Wge,
                          const float* __restrict__ Wue, const float* __restrict__ Wde) {
    int id = blockIdx.x;
    const float* src; __nv_bfloat16 *dh, *dl; int K, N, tile;
    if (id < 1024)      { src = Wgs; dh = d_Wgs_h; dl = d_Wgs_l; K = DIM; N = DS;  tile = id; }
    else if (id < 2048) { src = Wus; dh = d_Wus_h; dl = d_Wus_l; K = DIM; N = DS;  tile = id - 1024; }
    else if (id < 3072) { src = Wds; dh = d_Wds_h; dl = d_Wds_l; K = DS;  N = DIM; tile = id - 2048; }
    else if (id < 7168) {
        int l = id - 3072; int b = l >> 9; tile = l & 511; K = DIM; N = DE;
        src = Wge + (size_t)b * DIM * DE; dh = d_Wge_h + (size_t)b * DE * DIM; dl = d_Wge_l + (size_t)b * DE * DIM;
    } else if (id < 11264) {
        int l = id - 7168; int b = l >> 9; tile = l & 511; K = DIM; N = DE;
        src = Wue + (size_t)b * DIM * DE; dh = d_Wue_h + (size_t)b * DE * DIM; dl = d_Wue_l + (size_t)b * DE * DIM;
    } else {
        int l = id - 11264; int b = l >> 9; tile = l & 511; K = DE; N = DIM;
        src = Wde + (size_t)b * DE * DIM; dh = d_Wde_h + (size_t)b * DIM * DE; dl = d_Wde_l + (size_t)b * DIM * DE;
    }
    int tilesX = N / 32;
    int n0 = (tile % tilesX) * 32, k0 = (tile / tilesX) * 32;
    __shared__ float t[32][33];
    int tx = threadIdx.x, ty = threadIdx.y;
    #pragma unroll
    for (int i = 0; i < 32; i += 8) t[ty + i][tx] = src[(size_t)(k0 + ty + i) * N + n0 + tx];
    __syncthreads();
    #pragma unroll
    for (int i = 0; i < 32; i += 8) {
        float v = t[tx][ty + i];
        __nv_bfloat16 h, l; split2(v, h, l);
        size_t o = (size_t)(n0 + ty + i) * K + k0 + tx;
        dh[o] = h; dl[o] = l;
    }
}

__device__ __forceinline__ float silu(float g) { return g * (1.f / (1.f + expf(-g))); }

__global__ void combine_kernel(float* __restrict__ out) {
    int n = blockIdx.x;
    int t = threadIdx.x;
    int s0 = d_slot[2 * n], s1 = d_slot[2 * n + 1];
    float4* o4 = (float4*)(out + (size_t)n * DIM);
    const float4* r0 = (const float4*)(d_R + (size_t)s0 * DIM);
    const float4* r1 = (const float4*)(d_R + (size_t)s1 * DIM);
    float4 a = o4[t], b = r0[t], c = r1[t];
    a.x += b.x + c.x; a.y += b.y + c.y; a.z += b.z + c.z; a.w += b.w + c.w;
    o4[t] = a;
}

// ============================================================
// smem layout: each 128B row = [hi 64B | lo 64B] of one logical row, SW128.
// K-chunk 32 elems (64B per h/l). 3-stage cp.async pipeline, 2 CTAs/SM.
// ============================================================

// ---------------- hidden GEMM ----------------
// tile M128 x N64 per matrix (g,u); 8 warps 2x4, warp 64x16.
// z=0: dense shared; z=1..8: expert gathered (weight-folded epilogue).
#define H_A   0
#define H_BG  16384
#define H_BU  24576
#define H_STG 32768
#define H_TOT (3 * H_STG)

__global__ void __launch_bounds__(256, 2) hidden_gemm() {
    extern __shared__ char sm[];
    int tid = threadIdx.x, lane = tid & 31, wid = tid >> 5;
    int wm = wid >> 2, wn = wid & 3;
    int z = blockIdx.z, bx = blockIdx.x;
    int m0 = blockIdx.y * 128;
    bool routed = (z > 0);

    const __nv_bfloat16 *Bgh, *Bgl, *Buh, *Bul;
    __nv_bfloat16 *Hh, *Hl;
    int ldOut, cRowBase, mValid;
    const int K = DIM;

    int part = tid & 7, sub = part & 3, isLo = part >> 2;
    int r0 = tid >> 3;                     // 0..31

    uint32_t aOff[4];                      // A row byte offsets (4 rows: r0+32i)
    if (!routed) {
        Bgh = d_Wgs_h; Bgl = d_Wgs_l; Buh = d_Wus_h; Bul = d_Wus_l;
        Hh = d_Hs_h; Hl = d_Hs_l; ldOut = DS;
        mValid = 128; cRowBase = m0;
        #pragma unroll
        for (int i = 0; i < 4; i++) aOff[i] = (uint32_t)(m0 + r0 + 32 * i) * (DIM * 2);
    } else {
        if (bx >= DE / 64) return;
        int e = z - 1;
        int cnt = d_ecnt[e], off = e * ECAP;
        if (m0 >= cnt) return;
        size_t wb = (size_t)e * DE * DIM;
        Bgh = d_Wge_h + wb; Bgl = d_Wge_l + wb; Buh = d_Wue_h + wb; Bul = d_Wue_l + wb;
        Hh = d_Hr_h; Hl = d_Hr_l; ldOut = DE;
        mValid = cnt - m0; if (mValid > 128) mValid = 128;
        cRowBase = off + m0;
        #pragma unroll
        for (int i = 0; i < 4; i++) {
            int m = m0 + r0 + 32 * i; if (m > cnt - 1) m = cnt - 1;
            aOff[i] = (uint32_t)d_etok[off + m] * (DIM * 2);
        }
    }
    int n0 = bx * 64;
    Bgh += (size_t)n0 * K; Bgl += (size_t)n0 * K;
    Buh += (size_t)n0 * K; Bul += (size_t)n0 * K;

    uint32_t sbase = sm2u32(sm);
    const char* aBase = (const char*)(isLo ? d_xl : d_xh) + sub * 16;
    const char* bgP = (const char*)(isLo ? Bgl : Bgh) + (size_t)r0 * (K * 2) + sub * 16;
    const char* buP = (const char*)(isLo ? Bul : Buh) + (size_t)r0 * (K * 2) + sub * 16;
    uint32_t aS0 = SWZ((uint32_t)(r0 * 128 + part * 16));   // +i*4096 per extra row
    const int bRowStride = 32 * K * 2;

    const int nChunks = K / 32;

    // prologue: stages 0,1 (chunks 0,1)
    #pragma unroll
    for (int c = 0; c < 2; c++) {
        uint32_t sb = sbase + c * H_STG;
        #pragma unroll
        for (int i = 0; i < 4; i++) CPA16(sb + H_A + aS0 + i * 4096, aBase + aOff[i] + c * 64);
        #pragma unroll
        for (int i = 0; i < 2; i++) CPA16(sb + H_BG + aS0 + i * 4096, bgP + i * bRowStride + c * 64);
        #pragma unroll
        for (int i = 0; i < 2; i++) CPA16(sb + H_BU + aS0 + i * 4096, buP + i * bRowStride + c * 64);
        CPCOMMIT();
    }

    float ag[4][2][4], au[4][2][4];
    #pragma unroll
    for (int a = 0; a < 4; a++)
        #pragma unroll
        for (int b = 0; b < 2; b++)
            #pragma unroll
            for (int cR = 0; cR < 4; cR++) { ag[a][b][cR] = 0.f; au[a][b][cR] = 0.f; }

    int aRowB = wm * 64 + (lane & 15);
    uint32_t aCol = ((lane >> 4) & 1) * 16;        // byte col within 64B half
    int bRowB = wn * 16 + (lane & 7) + ((lane >> 4) << 3);
    uint32_t bCol = ((lane >> 3) & 1) * 16;

    int st = 0;
    for (int c = 0; c < nChunks; c++) {
        if (c + 2 < nChunks) {
            int pf = (st == 0) ? 2 : st - 1;       // (c+2)%3
            uint32_t sb = sbase + pf * H_STG;
            int cc = c + 2;
            #pragma unroll
            for (int i = 0; i < 4; i++) CPA16(sb + H_A + aS0 + i * 4096, aBase + aOff[i] + cc * 64);
            #pragma unroll
            for (int i = 0; i < 2; i++) CPA16(sb + H_BG + aS0 + i * 4096, bgP + i * bRowStride + cc * 64);
            #pragma unroll
            for (int i = 0; i < 2; i++) CPA16(sb + H_BU + aS0 + i * 4096, buP + i * bRowStride + cc * 64);
            CPCOMMIT();
            CPWAIT2();
        } else if (c + 1 < nChunks) {
            CPWAIT1();
        } else {
            CPWAIT0();
        }
        __syncthreads();

        uint32_t sb = sbase + st * H_STG;
        #pragma unroll
        for (int ks = 0; ks < 2; ks++) {
            uint32_t bgh[4], bgl[4], buh[4], bul[4];
            {
                uint32_t rb = (uint32_t)(bRowB * 128 + ks * 32 + bCol);
                LDMX4(bgh, sb + H_BG + SWZ(rb));
                LDMX4(bgl, sb + H_BG + SWZ(rb + 64));
                LDMX4(buh, sb + H_BU + SWZ(rb));
                LDMX4(bul, sb + H_BU + SWZ(rb + 64));
            }
            #pragma unroll
            for (int mt = 0; mt < 4; mt++) {
                uint32_t ah[4], al[4];
                uint32_t rb = (uint32_t)((aRowB + mt * 16) * 128 + ks * 32 + aCol);
                LDMX4(ah, sb + H_A + SWZ(rb));
                LDMX4(al, sb + H_A + SWZ(rb + 64));
                #pragma unroll
                for (int n8 = 0; n8 < 2; n8++) {
                    int j = n8 * 2;
                    MMA16816(ag[mt][n8], ah, bgh[j], bgh[j + 1]);
                    MMA16816(ag[mt][n8], ah, bgl[j], bgl[j + 1]);
                    MMA16816(ag[mt][n8], al, bgh[j], bgh[j + 1]);
                    MMA16816(au[mt][n8], ah, buh[j], buh[j + 1]);
                    MMA16816(au[mt][n8], ah, bul[j], bul[j + 1]);
                    MMA16816(au[mt][n8], al, buh[j], buh[j + 1]);
                }
            }
        }
        __syncthreads();
        st = (st == 2) ? 0 : st + 1;
    }

    #pragma unroll
    for (int mt = 0; mt < 4; mt++) {
        #pragma unroll
        for (int h = 0; h < 2; h++) {
            int rIn = wm * 64 + mt * 16 + (lane >> 2) + h * 8;
            if (rIn < mValid) {
                float wt = routed ? d_ewt[cRowBase + rIn] : 1.0f;
                size_t rowOff = (size_t)(cRowBase + rIn) * ldOut;
                #pragma unroll
                for (int n8 = 0; n8 < 2; n8++) {
                    int col = n0 + wn * 16 + n8 * 8 + (lane & 3) * 2;
                    float v0 = wt * silu(ag[mt][n8][h * 2 + 0]) * au[mt][n8][h * 2 + 0];
                    float v1 = wt * silu(ag[mt][n8][h * 2 + 1]) * au[mt][n8][h * 2 + 1];
                    __nv_bfloat16 h0, l0, h1, l1;
                    split2(v0, h0, l0); split2(v1, h1, l1);
                    __nv_bfloat162 hv; hv.x = h0; hv.y = h1;
                    __nv_bfloat162 lv; lv.x = l0; lv.y = l1;
                    *(__nv_bfloat162*)(Hh + rowOff + col) = hv;
                    *(__nv_bfloat162*)(Hl + rowOff + col) = lv;
                }
            }
        }
    }
}

// ---------------- down GEMM ----------------
// tile 128x128; 8 warps 2x4, warp 64x32. z=0 dense -> out; z=1..8 routed -> R.
#define D_A   0
#define D_B   16384
#define D_STG 32768
#define D_TOT (3 * D_STG)

__global__ void __launch_bounds__(256, 2) down_gemm(float* __restrict__ out) {
    extern __shared__ char sm[];
    int tid = threadIdx.x, lane = tid & 31, wid = tid >> 5;
    int wm = wid >> 2, wn = wid & 3;
    int z = blockIdx.z;
    int m0 = blockIdx.y * 128;
    bool routed = (z > 0);

    const __nv_bfloat16 *Ah, *Al, *Bh, *Bl;
    float* C;
    int K, mValid, cRowBase;

    int part = tid & 7, sub = part & 3, isLo = part >> 2;
    int r0 = tid >> 3;

    uint32_t aOff[4];
    if (!routed) {
        Ah = d_Hs_h; Al = d_Hs_l; K = DS;
        Bh = d_Wds_h; Bl = d_Wds_l;
        C = out;
        mValid = 128; cRowBase = m0;
        #pragma unroll
        for (int i = 0; i < 4; i++) aOff[i] = (uint32_t)(m0 + r0 + 32 * i) * (DS * 2);
    } else {
        int e = z - 1;
        int cnt = d_ecnt[e], off = e * ECAP;
        if (m0 >= cnt) return;
        Ah = d_Hr_h; Al = d_Hr_l; K = DE;
        Bh = d_Wde_h + (size_t)e * DIM * DE; Bl = d_Wde_l + (size_t)e * DIM * DE;
        C = d_R;
        mValid = cnt - m0; if (mValid > 128) mValid = 128;
        cRowBase = off + m0;
        #pragma unroll
        for (int i = 0; i < 4; i++) {
            int m = m0 + r0 + 32 * i; if (m > cnt - 1) m = cnt - 1;
            aOff[i] = (uint32_t)(off + m) * (DE * 2);
        }
    }
    int n0 = blockIdx.x * 128;
    Bh += (size_t)n0 * K;
    Bl += (size_t)n0 * K;

    uint32_t sbase = sm2u32(sm);
    const char* aBase = (const char*)(isLo ? Al : Ah) + sub * 16;
    const char* bP = (const char*)(isLo ? Bl : Bh) + (size_t)r0 * (K * 2) + sub * 16;
    uint32_t aS0 = SWZ((uint32_t)(r0 * 128 + part * 16));
    const int bRowStride = 32 * K * 2;

    int nChunks = K / 32;

    #pragma unroll
    for (int c = 0; c < 2; c++) {
        uint32_t sb = sbase + c * D_STG;
        #pragma unroll
        for (int i = 0; i < 4; i++) CPA16(sb + D_A + aS0 + i * 4096, aBase + aOff[i] + c * 64);
        #pragma unroll
        for (int i = 0; i < 4; i++) CPA16(sb + D_B + aS0 + i * 4096, bP + i * bRowStride + c * 64);
        CPCOMMIT();
    }

    float acc[4][4][4];
    #pragma unroll
    for (int a = 0; a < 4; a++)
        #pragma unroll
        for (int b = 0; b < 4; b++)
            #pragma unroll
            for (int cR = 0; cR < 4; cR++) acc[a][b][cR] = 0.f;

    int aRowB = wm * 64 + (lane & 15);
    uint32_t aCol = ((lane >> 4) & 1) * 16;
    int bRowB = wn * 32 + (lane & 7) + ((lane >> 4) << 3);
    uint32_t bCol = ((lane >> 3) & 1) * 16;

    int st = 0;
    for (int c = 0; c < nChunks; c++) {
        if (c + 2 < nChunks) {
            int pf = (st == 0) ? 2 : st - 1;
            uint32_t sb = sbase + pf * D_STG;
            int cc = c + 2;
            #pragma unroll
            for (int i = 0; i < 4; i++) CPA16(sb + D_A + aS0 + i * 4096, aBase + aOff[i] + cc * 64);
            #pragma unroll
            for (int i = 0; i < 4; i++) CPA16(sb + D_B + aS0 + i * 4096, bP + i * bRowStride + cc * 64);
            CPCOMMIT();
            CPWAIT2();
        } else if (c + 1 < nChunks) {
            CPWAIT1();
        } else {
            CPWAIT0();
        }
        __syncthreads();

        uint32_t sb = sbase + st * D_STG;
        #pragma unroll
        for (int ks = 0; ks < 2; ks++) {
            uint32_t bh[2][4], bl[2][4];
            #pragma unroll
            for (int g = 0; g < 2; g++) {
                uint32_t rb = (uint32_t)((bRowB + g * 16) * 128 + ks * 32 + bCol);
                LDMX4(bh[g], sb + D_B + SWZ(rb));
                LDMX4(bl[g], sb + D_B + SWZ(rb + 64));
            }
            #pragma unroll
            for (int mt = 0; mt < 4; mt++) {
                uint32_t ah[4], al[4];
                uint32_t rb = (uint32_t)((aRowB + mt * 16) * 128 + ks * 32 + aCol);
                LDMX4(ah, sb + D_A + SWZ(rb));
                LDMX4(al, sb + D_A + SWZ(rb + 64));
                #pragma unroll
                for (int n8 = 0; n8 < 4; n8++) {
                    int g = n8 >> 1, j = (n8 & 1) * 2;
                    MMA16816(acc[mt][n8], ah, bh[g][j], bh[g][j + 1]);
                    MMA16816(acc[mt][n8], ah, bl[g][j], bl[g][j + 1]);
                    MMA16816(acc[mt][n8], al, bh[g][j], bh[g][j + 1]);
                }
            }
        }
        __syncthreads();
        st = (st == 2) ? 0 : st + 1;
    }

    #pragma unroll
    for (int mt = 0; mt < 4; mt++) {
        #pragma unroll
        for (int h = 0; h < 2; h++) {
            int rIn = wm * 64 + mt * 16 + (lane >> 2) + h * 8;
            if (rIn < mValid) {
                float* p = C + (size_t)(cRowBase + rIn) * DIM + n0 + wn * 32 + (lane & 3) * 2;
                #pragma unroll
                for (int n8 = 0; n8 < 4; n8++) {
                    float2 v; v.x = acc[mt][n8][h * 2 + 0]; v.y = acc[mt][n8][h * 2 + 1];
                    *(float2*)(p + n8 * 8) = v;
                }
            }
        }
    }
}

// ----------------- launch -----------------
extern "C" void kernel_launch(void* const* d_in, const int* in_sizes, int n_in,
                              void* d_out, int out_size) {
    const float* x   = (const float*)d_in[0];
    const float* Wg  = (const float*)d_in[1];
    const float* Wge = (const float*)d_in[2];
    const float* Wue = (const float*)d_in[3];
    const float* Wde = (const float*)d_in[4];
    const float* Wgs = (const float*)d_in[5];
    const float* Wus = (const float*)d_in[6];
    const float* Wds = (const float*)d_in[7];
    float* out = (float*)d_out;

    cudaFuncSetAttribute(hidden_gemm, cudaFuncAttributeMaxDynamicSharedMemorySize, H_TOT);
    cudaFuncSetAttribute(down_gemm,   cudaFuncAttributeMaxDynamicSharedMemorySize, D_TOT);

    void* ecnt_ptr;
    cudaGetSymbolAddress(&ecnt_ptr, d_ecnt);
    cudaMemsetAsync(ecnt_ptr, 0, NE * sizeof(int), 0);

    convT_all<<<15360, dim3(32, 8)>>>(Wgs, Wus, Wds, Wge, Wue, Wde);     // 1
    gate_kernel<<<N_TOK, 256>>>(x, Wg);                                  // 2
    hidden_gemm<<<dim3(16, 16, 9), 256, H_TOT>>>();                      // 3
    down_gemm<<<dim3(8, 16, 9), 256, D_TOT>>>(out);                      // 4  <- profiled
    combine_kernel<<<N_TOK, 256>>>(out);                                 // 5
}

// round 8
// speedup vs baseline: 3.4817x; 1.1823x over previous
#include <cuda_runtime.h>
#include <cuda_fp16.h>
#include <math.h>
#include <stdint.h>

#define N_TOK 2048
#define DIM   1024
#define DE    512
#define DS    1024
#define NE    8
#define NSLOT (N_TOK * 2)
#define ECAP  2048

// ----------------- scratch (device globals; no allocs) -----------------
__device__ int   d_ecnt[NE];                 // zeroed via cudaMemsetAsync
__device__ int   d_etok[NE * ECAP];
__device__ float d_ewt [NE * ECAP];
__device__ int   d_slot[NSLOT];

__device__ __half d_xh[N_TOK * DIM], d_xl[N_TOK * DIM];   // x split hi+lo (exact-ish)
__device__ __half d_Wgs[DS * DIM];                        // weights single fp16, [N][K]
__device__ __half d_Wus[DS * DIM];
__device__ __half d_Wds[DIM * DS];
__device__ __half d_Wge[NE * DE * DIM];
__device__ __half d_Wue[NE * DE * DIM];
__device__ __half d_Wde[NE * DIM * DE];

__device__ __half d_Hs_h[N_TOK * DS], d_Hs_l[N_TOK * DS];
__device__ __half d_Hr_h[NE * ECAP * DE], d_Hr_l[NE * ECAP * DE];
__device__ float d_R [NE * ECAP * DIM];

// ----------------- asm helpers -----------------
__device__ __forceinline__ uint32_t sm2u32(const void* p) {
    uint32_t a;
    asm("{ .reg .u64 t; cvta.to.shared.u64 t, %1; cvt.u32.u64 %0, t; }" : "=r"(a) : "l"(p));
    return a;
}
#define SWZ(o) ((o) ^ (((o) >> 3) & 0x70))

#define CPA16(s, g)  asm volatile("cp.async.cg.shared.global [%0], [%1], 16;" :: "r"(s), "l"(g))
#define CPCOMMIT()   asm volatile("cp.async.commit_group;" ::: "memory")
#define CPWAIT1()    asm volatile("cp.async.wait_group 1;" ::: "memory")
#define CPWAIT0()    asm volatile("cp.async.wait_group 0;" ::: "memory")

#define LDMX4(r, a) \
    asm volatile("ldmatrix.sync.aligned.m8n8.x4.shared.b16 {%0,%1,%2,%3}, [%4];" \
        : "=r"((r)[0]), "=r"((r)[1]), "=r"((r)[2]), "=r"((r)[3]) : "r"(a))

#define MMAF16(c, a, b0, b1) \
    asm volatile("mma.sync.aligned.m16n8k16.row.col.f32.f16.f16.f32 " \
        "{%0,%1,%2,%3},{%4,%5,%6,%7},{%8,%9},{%0,%1,%2,%3};" \
        : "+f"((c)[0]), "+f"((c)[1]), "+f"((c)[2]), "+f"((c)[3]) \
        : "r"((a)[0]), "r"((a)[1]), "r"((a)[2]), "r"((a)[3]), "r"(b0), "r"(b1))

__device__ __forceinline__ void splitH(float v, __half& h, __half& l) {
    h = __float2half(v);
    l = __float2half(v - __half2float(h));
}

// ----------------- gate + convX + routing (fused) -----------------
__global__ void gate_kernel(const float* __restrict__ x, const float* __restrict__ Wg) {
    int n = blockIdx.x;
    int t = threadIdx.x;
    __shared__ float xs[DIM];
    __shared__ float logits[NE];
    float4 v = ((const float4*)(x + (size_t)n * DIM))[t];
    ((float4*)xs)[t] = v;
    {
        __half h0,h1,h2,h3,l0,l1,l2,l3;
        splitH(v.x,h0,l0); splitH(v.y,h1,l1); splitH(v.z,h2,l2); splitH(v.w,h3,l3);
        size_t o = (size_t)n * DIM + t * 4;
        __half2 a, b;
        a.x=h0; a.y=h1; b.x=h2; b.y=h3;
        *(__half2*)(d_xh + o) = a; *(__half2*)(d_xh + o + 2) = b;
        a.x=l0; a.y=l1; b.x=l2; b.y=l3;
        *(__half2*)(d_xl + o) = a; *(__half2*)(d_xl + o + 2) = b;
    }
    __syncthreads();
    int w = t >> 5, l = t & 31;
    float s = 0.f;
    for (int d = l; d < DIM; d += 32) s += xs[d] * Wg[d * NE + w];
    #pragma unroll
    for (int o = 16; o; o >>= 1) s += __shfl_xor_sync(0xffffffffu, s, o);
    if (l == 0) logits[w] = s;
    __syncthreads();
    if (t == 0) {
        float mx = logits[0];
        #pragma unroll
        for (int e = 1; e < NE; e++) mx = fmaxf(mx, logits[e]);
        float p[NE], den = 0.f;
        #pragma unroll
        for (int e = 0; e < NE; e++) { p[e] = expf(logits[e] - mx); den += p[e]; }
        float inv = 1.f / den;
        int i0 = 0;
        #pragma unroll
        for (int e = 1; e < NE; e++) if (p[e] > p[i0]) i0 = e;
        int i1 = (i0 == 0) ? 1 : 0;
        #pragma unroll
        for (int e = 0; e < NE; e++) if (e != i0 && p[e] > p[i1]) i1 = e;
        int p0 = atomicAdd(&d_ecnt[i0], 1);
        int s0 = i0 * ECAP + p0;
        d_etok[s0] = n; d_ewt[s0] = p[i0] * inv; d_slot[2*n] = s0;
        int p1 = atomicAdd(&d_ecnt[i1], 1);
        int s1 = i1 * ECAP + p1;
        d_etok[s1] = n; d_ewt[s1] = p[i1] * inv; d_slot[2*n+1] = s1;
    }
}

// weight transposes, one launch: src [K][N] fp32 -> [N][K] fp16 (single)
__global__ void convT_all(const float* __restrict__ Wgs, const float* __restrict__ Wus,
                          const float* __restrict__ Wds, const float* __restrict__ Wge,
                          const float* __restrict__ Wue, const float* __restrict__ Wde) {
    int id = blockIdx.x;
    const float* src; __half* dh; int K, N, tile;
    if (id < 1024)      { src = Wgs; dh = d_Wgs; K = DIM; N = DS;  tile = id; }
    else if (id < 2048) { src = Wus; dh = d_Wus; K = DIM; N = DS;  tile = id - 1024; }
    else if (id < 3072) { src = Wds; dh = d_Wds; K = DS;  N = DIM; tile = id - 2048; }
    else if (id < 7168) {
        int l = id - 3072; int b = l >> 9; tile = l & 511; K = DIM; N = DE;
        src = Wge + (size_t)b * DIM * DE; dh = d_Wge + (size_t)b * DE * DIM;
    } else if (id < 11264) {
        int l = id - 7168; int b = l >> 9; tile = l & 511; K = DIM; N = DE;
        src = Wue + (size_t)b * DIM * DE; dh = d_Wue + (size_t)b * DE * DIM;
    } else {
        int l = id - 11264; int b = l >> 9; tile = l & 511; K = DE; N = DIM;
        src = Wde + (size_t)b * DE * DIM; dh = d_Wde + (size_t)b * DIM * DE;
    }
    int tilesX = N / 32;
    int n0 = (tile % tilesX) * 32, k0 = (tile / tilesX) * 32;
    __shared__ float t[32][33];
    int tx = threadIdx.x, ty = threadIdx.y;
    #pragma unroll
    for (int i = 0; i < 32; i += 8) t[ty + i][tx] = src[(size_t)(k0 + ty + i) * N + n0 + tx];
    __syncthreads();
    #pragma unroll
    for (int i = 0; i < 32; i += 8) {
        dh[(size_t)(n0 + ty + i) * K + k0 + tx] = __float2half(t[tx][ty + i]);
    }
}

__device__ __forceinline__ float silu(float g) { return g * (1.f / (1.f + expf(-g))); }

__global__ void combine_kernel(float* __restrict__ out) {
    int n = blockIdx.x;
    int t = threadIdx.x;
    int s0 = d_slot[2 * n], s1 = d_slot[2 * n + 1];
    float4* o4 = (float4*)(out + (size_t)n * DIM);
    const float4* r0 = (const float4*)(d_R + (size_t)s0 * DIM);
    const float4* r1 = (const float4*)(d_R + (size_t)s1 * DIM);
    float4 a = o4[t], b = r0[t], c = r1[t];
    a.x += b.x + c.x; a.y += b.y + c.y; a.z += b.z + c.z; a.w += b.w + c.w;
    o4[t] = a;
}

// ============================================================
// GEMMs: fp16 2-term (A = Ah + Al exact split; B single fp16).
// K-chunk 64 (128B rows, SW128), 2-stage cp.async, 2 CTAs/SM.
// ============================================================

// ---------------- hidden GEMM ----------------
// tile M128 x N64 per matrix; 8 warps 2x4, warp 64x16.
#define H_AH  0
#define H_AL  16384
#define H_BG  32768
#define H_BU  40960
#define H_STG 49152
#define H_TOT (2 * H_STG)

__global__ void __launch_bounds__(256, 2) hidden_gemm() {
    extern __shared__ char sm[];
    int tid = threadIdx.x, lane = tid & 31, wid = tid >> 5;
    int wm = wid >> 2, wn = wid & 3;
    int z = blockIdx.z, bx = blockIdx.x;
    int m0 = blockIdx.y * 128;
    bool routed = (z > 0);

    const __half *Bg, *Bu;
    __half *Hh, *Hl;
    int ldOut, cRowBase, mValid;
    const int K = DIM;

    int ldRow = tid >> 1, ldHalf = tid & 1;      // A / generic 128-row loader
    int aTok;

    if (!routed) {
        Bg = d_Wgs; Bu = d_Wus;
        Hh = d_Hs_h; Hl = d_Hs_l; ldOut = DS;
        mValid = 128; cRowBase = m0;
        aTok = m0 + ldRow;
    } else {
        if (bx >= DE / 64) return;
        int e = z - 1;
        int cnt = d_ecnt[e], off = e * ECAP;
        if (m0 >= cnt) return;
        size_t wb = (size_t)e * DE * DIM;
        Bg = d_Wge + wb; Bu = d_Wue + wb;
        Hh = d_Hr_h; Hl = d_Hr_l; ldOut = DE;
        mValid = cnt - m0; if (mValid > 128) mValid = 128;
        cRowBase = off + m0;
        int m = m0 + ldRow; if (m > cnt - 1) m = cnt - 1;
        aTok = d_etok[off + m];
    }
    int n0 = bx * 64;
    Bg += (size_t)n0 * K; Bu += (size_t)n0 * K;

    uint32_t sbase = sm2u32(sm);
    const char* aGh = (const char*)(d_xh + (size_t)aTok * DIM) + ldHalf * 64;
    const char* aGl = (const char*)(d_xl + (size_t)aTok * DIM) + ldHalf * 64;
    uint32_t soff[4];
    #pragma unroll
    for (int i = 0; i < 4; i++) soff[i] = SWZ((uint32_t)(ldRow * 128 + ldHalf * 64 + i * 16));
    // B loader: 64 rows, 4 threads/row
    int bRow = tid >> 2, bQ = tid & 3;
    const char* bgP = (const char*)Bg + (size_t)bRow * (K * 2) + bQ * 32;
    const char* buP = (const char*)Bu + (size_t)bRow * (K * 2) + bQ * 32;
    uint32_t sB[2];
    #pragma unroll
    for (int j = 0; j < 2; j++) sB[j] = SWZ((uint32_t)(bRow * 128 + bQ * 32 + j * 16));

    const int nChunks = K / 64;

    // prologue: stage 0 <- chunk 0
    {
        uint32_t sb = sbase;
        #pragma unroll
        for (int i = 0; i < 4; i++) {
            CPA16(sb + H_AH + soff[i], aGh + i * 16);
            CPA16(sb + H_AL + soff[i], aGl + i * 16);
        }
        #pragma unroll
        for (int j = 0; j < 2; j++) {
            CPA16(sb + H_BG + sB[j], bgP + j * 16);
            CPA16(sb + H_BU + sB[j], buP + j * 16);
        }
        CPCOMMIT();
    }

    float ag[4][2][4], au[4][2][4];
    #pragma unroll
    for (int a = 0; a < 4; a++)
        #pragma unroll
        for (int b = 0; b < 2; b++)
            #pragma unroll
            for (int cR = 0; cR < 4; cR++) { ag[a][b][cR] = 0.f; au[a][b][cR] = 0.f; }

    int aRowB = wm * 64 + (lane & 15);
    uint32_t aCol = ((lane >> 4) & 1) * 16;
    int bRowB = wn * 16 + (lane & 7) + ((lane >> 4) << 3);
    uint32_t bCol = ((lane >> 3) & 1) * 16;

    for (int c = 0; c < nChunks; c++) {
        if (c + 1 < nChunks) {
            uint32_t sb = sbase + ((c + 1) & 1) * H_STG;
            int kb = (c + 1) * 128;
            #pragma unroll
            for (int i = 0; i < 4; i++) {
                CPA16(sb + H_AH + soff[i], aGh + kb + i * 16);
                CPA16(sb + H_AL + soff[i], aGl + kb + i * 16);
            }
            #pragma unroll
            for (int j = 0; j < 2; j++) {
                CPA16(sb + H_BG + sB[j], bgP + kb + j * 16);
                CPA16(sb + H_BU + sB[j], buP + kb + j * 16);
            }
            CPCOMMIT();
            CPWAIT1();
        } else {
            CPWAIT0();
        }
        __syncthreads();

        uint32_t sb = sbase + (c & 1) * H_STG;
        #pragma unroll
        for (int ks = 0; ks < 4; ks++) {
            uint32_t bg[4], bu[4];
            {
                uint32_t rb = (uint32_t)(bRowB * 128 + ks * 32 + bCol);
                LDMX4(bg, sb + H_BG + SWZ(rb));
                LDMX4(bu, sb + H_BU + SWZ(rb));
            }
            #pragma unroll
            for (int mt = 0; mt < 4; mt++) {
                uint32_t ah[4], al[4];
                uint32_t rb = (uint32_t)((aRowB + mt * 16) * 128 + ks * 32 + aCol);
                LDMX4(ah, sb + H_AH + SWZ(rb));
                LDMX4(al, sb + H_AL + SWZ(rb));
                #pragma unroll
                for (int n8 = 0; n8 < 2; n8++) {
                    int j = n8 * 2;
                    MMAF16(ag[mt][n8], ah, bg[j], bg[j + 1]);
                    MMAF16(ag[mt][n8], al, bg[j], bg[j + 1]);
                    MMAF16(au[mt][n8], ah, bu[j], bu[j + 1]);
                    MMAF16(au[mt][n8], al, bu[j], bu[j + 1]);
                }
            }
        }
        __syncthreads();
    }

    #pragma unroll
    for (int mt = 0; mt < 4; mt++) {
        #pragma unroll
        for (int h = 0; h < 2; h++) {
            int rIn = wm * 64 + mt * 16 + (lane >> 2) + h * 8;
            if (rIn < mValid) {
                float wt = routed ? d_ewt[cRowBase + rIn] : 1.0f;
                size_t rowOff = (size_t)(cRowBase + rIn) * ldOut;
                #pragma unroll
                for (int n8 = 0; n8 < 2; n8++) {
                    int col = n0 + wn * 16 + n8 * 8 + (lane & 3) * 2;
                    float v0 = wt * silu(ag[mt][n8][h * 2 + 0]) * au[mt][n8][h * 2 + 0];
                    float v1 = wt * silu(ag[mt][n8][h * 2 + 1]) * au[mt][n8][h * 2 + 1];
                    __half h0, l0, h1, l1;
                    splitH(v0, h0, l0); splitH(v1, h1, l1);
                    __half2 hv; hv.x = h0; hv.y = h1;
                    __half2 lv; lv.x = l0; lv.y = l1;
                    *(__half2*)(Hh + rowOff + col) = hv;
                    *(__half2*)(Hl + rowOff + col) = lv;
                }
            }
        }
    }
}

// ---------------- down GEMM ----------------
// tile 128x128; 8 warps 2x4, warp 64x32. z=0 dense -> out; z=1..8 routed -> R.
#define D_AH  0
#define D_AL  16384
#define D_B   32768
#define D_STG 49152
#define D_TOT (2 * D_STG)

__global__ void __launch_bounds__(256, 2) down_gemm(float* __restrict__ out) {
    extern __shared__ char sm[];
    int tid = threadIdx.x, lane = tid & 31, wid = tid >> 5;
    int wm = wid >> 2, wn = wid & 3;
    int z = blockIdx.z;
    int m0 = blockIdx.y * 128;
    bool routed = (z > 0);

    const __half *Ah, *Al, *B;
    float* C;
    int K, mValid, cRowBase, aRowLd;

    int ldRow = tid >> 1, ldHalf = tid & 1;

    if (!routed) {
        Ah = d_Hs_h; Al = d_Hs_l; K = DS;
        B = d_Wds;
        C = out;
        mValid = 128; cRowBase = m0;
        aRowLd = m0 + ldRow;
    } else {
        int e = z - 1;
        int cnt = d_ecnt[e], off = e * ECAP;
        if (m0 >= cnt) return;
        Ah = d_Hr_h; Al = d_Hr_l; K = DE;
        B = d_Wde + (size_t)e * DIM * DE;
        C = d_R;
        mValid = cnt - m0; if (mValid > 128) mValid = 128;
        cRowBase = off + m0;
        int m = m0 + ldRow; if (m > cnt - 1) m = cnt - 1;
        aRowLd = off + m;
    }
    int n0 = blockIdx.x * 128;
    B += (size_t)n0 * K;

    uint32_t sbase = sm2u32(sm);
    const char* aGh = (const char*)(Ah + (size_t)aRowLd * K) + ldHalf * 64;
    const char* aGl = (const char*)(Al + (size_t)aRowLd * K) + ldHalf * 64;
    const char* bG  = (const char*)(B + (size_t)ldRow * K) + ldHalf * 64;
    uint32_t soff[4];
    #pragma unroll
    for (int i = 0; i < 4; i++) soff[i] = SWZ((uint32_t)(ldRow * 128 + ldHalf * 64 + i * 16));

    int nChunks = K / 64;

    {
        uint32_t sb = sbase;
        #pragma unroll
        for (int i = 0; i < 4; i++) {
            CPA16(sb + D_AH + soff[i], aGh + i * 16);
            CPA16(sb + D_AL + soff[i], aGl + i * 16);
            CPA16(sb + D_B  + soff[i], bG  + i * 16);
        }
        CPCOMMIT();
    }

    float acc[4][4][4];
    #pragma unroll
    for (int a = 0; a < 4; a++)
        #pragma unroll
        for (int b = 0; b < 4; b++)
            #pragma unroll
            for (int cR = 0; cR < 4; cR++) acc[a][b][cR] = 0.f;

    int aRowB = wm * 64 + (lane & 15);
    uint32_t aCol = ((lane >> 4) & 1) * 16;
    int bRowB = wn * 32 + (lane & 7) + ((lane >> 4) << 3);
    uint32_t bCol = ((lane >> 3) & 1) * 16;

    for (int c = 0; c < nChunks; c++) {
        if (c + 1 < nChunks) {
            uint32_t sb = sbase + ((c + 1) & 1) * D_STG;
            int kb = (c + 1) * 128;
            #pragma unroll
            for (int i = 0; i < 4; i++) {
                CPA16(sb + D_AH + soff[i], aGh + kb + i * 16);
                CPA16(sb + D_AL + soff[i], aGl + kb + i * 16);
                CPA16(sb + D_B  + soff[i], bG  + kb + i * 16);
            }
            CPCOMMIT();
            CPWAIT1();
        } else {
            CPWAIT0();
        }
        __syncthreads();

        uint32_t sb = sbase + (c & 1) * D_STG;
        #pragma unroll
        for (int ks = 0; ks < 4; ks++) {
            uint32_t b[2][4];
            #pragma unroll
            for (int g = 0; g < 2; g++) {
                uint32_t rb = (uint32_t)((bRowB + g * 16) * 128 + ks * 32 + bCol);
                LDMX4(b[g], sb + D_B + SWZ(rb));
            }
            #pragma unroll
            for (int mt = 0; mt < 4; mt++) {
                uint32_t ah[4], al[4];
                uint32_t rb = (uint32_t)((aRowB + mt * 16) * 128 + ks * 32 + aCol);
                LDMX4(ah, sb + D_AH + SWZ(rb));
                LDMX4(al, sb + D_AL + SWZ(rb));
                #pragma unroll
                for (int n8 = 0; n8 < 4; n8++) {
                    int g = n8 >> 1, j = (n8 & 1) * 2;
                    MMAF16(acc[mt][n8], ah, b[g][j], b[g][j + 1]);
                    MMAF16(acc[mt][n8], al, b[g][j], b[g][j + 1]);
                }
            }
        }
        __syncthreads();
    }

    #pragma unroll
    for (int mt = 0; mt < 4; mt++) {
        #pragma unroll
        for (int h = 0; h < 2; h++) {
            int rIn = wm * 64 + mt * 16 + (lane >> 2) + h * 8;
            if (rIn < mValid) {
                float* p = C + (size_t)(cRowBase + rIn) * DIM + n0 + wn * 32 + (lane & 3) * 2;
                #pragma unroll
                for (int n8 = 0; n8 < 4; n8++) {
                    float2 v; v.x = acc[mt][n8][h * 2 + 0]; v.y = acc[mt][n8][h * 2 + 1];
                    *(float2*)(p + n8 * 8) = v;
                }
            }
        }
    }
}

// ----------------- launch -----------------
extern "C" void kernel_launch(void* const* d_in, const int* in_sizes, int n_in,
                              void* d_out, int out_size) {
    const float* x   = (const float*)d_in[0];
    const float* Wg  = (const float*)d_in[1];
    const float* Wge = (const float*)d_in[2];
    const float* Wue = (const float*)d_in[3];
    const float* Wde = (const float*)d_in[4];
    const float* Wgs = (const float*)d_in[5];
    const float* Wus = (const float*)d_in[6];
    const float* Wds = (const float*)d_in[7];
    float* out = (float*)d_out;

    cudaFuncSetAttribute(hidden_gemm, cudaFuncAttributeMaxDynamicSharedMemorySize, H_TOT);
    cudaFuncSetAttribute(down_gemm,   cudaFuncAttributeMaxDynamicSharedMemorySize, D_TOT);

    void* ecnt_ptr;
    cudaGetSymbolAddress(&ecnt_ptr, d_ecnt);
    cudaMemsetAsync(ecnt_ptr, 0, NE * sizeof(int), 0);

    convT_all<<<15360, dim3(32, 8)>>>(Wgs, Wus, Wds, Wge, Wue, Wde);     // 1
    gate_kernel<<<N_TOK, 256>>>(x, Wg);                                  // 2
    hidden_gemm<<<dim3(16, 16, 9), 256, H_TOT>>>();                      // 3
    down_gemm<<<dim3(8, 16, 9), 256, D_TOT>>>(out);                      // 4  <- profiled
    combine_kernel<<<N_TOK, 256>>>(out);                                 // 5
}

// round 10
// speedup vs baseline: 4.0612x; 1.1664x over previous
#include <cuda_runtime.h>
#include <cuda_fp16.h>
#include <math.h>
#include <stdint.h>

#define N_TOK 2048
#define DIM   1024
#define DE    512
#define DS    1024
#define NE    8
#define NSLOT (N_TOK * 2)
#define ECAP  2048

// ----------------- scratch (device globals; no allocs) -----------------
__device__ int   d_ecnt[NE];                 // zeroed via cudaMemsetAsync
__device__ int   d_etok[NE * ECAP];
__device__ float d_ewt [NE * ECAP];
__device__ int   d_slot[NSLOT];

__device__ __half d_xh[N_TOK * DIM], d_xl[N_TOK * DIM];   // x split hi+lo
__device__ __half d_Wgs[DS * DIM];                        // weights fp16, [N][K]
__device__ __half d_Wus[DS * DIM];
__device__ __half d_Wds[DIM * DS];
__device__ __half d_Wge[NE * DE * DIM];
__device__ __half d_Wue[NE * DE * DIM];
__device__ __half d_Wde[NE * DIM * DE];

__device__ __half d_Hs_h[N_TOK * DS], d_Hs_l[N_TOK * DS];
__device__ __half d_Hr_h[NE * ECAP * DE], d_Hr_l[NE * ECAP * DE];
__device__ float d_R [NE * ECAP * DIM];

// ----------------- asm helpers -----------------
__device__ __forceinline__ uint32_t sm2u32(const void* p) {
    uint32_t a;
    asm("{ .reg .u64 t; cvta.to.shared.u64 t, %1; cvt.u32.u64 %0, t; }" : "=r"(a) : "l"(p));
    return a;
}
#define SWZ(o) ((o) ^ (((o) >> 3) & 0x70))

#define CPA16(s, g)  asm volatile("cp.async.cg.shared.global [%0], [%1], 16;" :: "r"(s), "l"(g))
#define CPCOMMIT()   asm volatile("cp.async.commit_group;" ::: "memory")
#define CPWAIT1()    asm volatile("cp.async.wait_group 1;" ::: "memory")
#define CPWAIT0()    asm volatile("cp.async.wait_group 0;" ::: "memory")

#define LDMX4(r, a) \
    asm volatile("ldmatrix.sync.aligned.m8n8.x4.shared.b16 {%0,%1,%2,%3}, [%4];" \
        : "=r"((r)[0]), "=r"((r)[1]), "=r"((r)[2]), "=r"((r)[3]) : "r"(a))

#define MMAF16(c, a, b0, b1) \
    asm volatile("mma.sync.aligned.m16n8k16.row.col.f32.f16.f16.f32 " \
        "{%0,%1,%2,%3},{%4,%5,%6,%7},{%8,%9},{%0,%1,%2,%3};" \
        : "+f"((c)[0]), "+f"((c)[1]), "+f"((c)[2]), "+f"((c)[3]) \
        : "r"((a)[0]), "r"((a)[1]), "r"((a)[2]), "r"((a)[3]), "r"(b0), "r"(b1))

__device__ __forceinline__ void splitH(float v, __half& h, __half& l) {
    h = __float2half(v);
    l = __float2half(v - __half2float(h));
}

// ----------------- gate + convX + routing (fused) -----------------
__global__ void gate_kernel(const float* __restrict__ x, const float* __restrict__ Wg) {
    int n = blockIdx.x;
    int t = threadIdx.x;
    __shared__ float xs[DIM];
    __shared__ float logits[NE];
    float4 v = ((const float4*)(x + (size_t)n * DIM))[t];
    ((float4*)xs)[t] = v;
    {
        __half h0,h1,h2,h3,l0,l1,l2,l3;
        splitH(v.x,h0,l0); splitH(v.y,h1,l1); splitH(v.z,h2,l2); splitH(v.w,h3,l3);
        size_t o = (size_t)n * DIM + t * 4;
        __half2 a, b;
        a.x=h0; a.y=h1; b.x=h2; b.y=h3;
        *(__half2*)(d_xh + o) = a; *(__half2*)(d_xh + o + 2) = b;
        a.x=l0; a.y=l1; b.x=l2; b.y=l3;
        *(__half2*)(d_xl + o) = a; *(__half2*)(d_xl + o + 2) = b;
    }
    __syncthreads();
    int w = t >> 5, l = t & 31;
    float s = 0.f;
    for (int d = l; d < DIM; d += 32) s += xs[d] * Wg[d * NE + w];
    #pragma unroll
    for (int o = 16; o; o >>= 1) s += __shfl_xor_sync(0xffffffffu, s, o);
    if (l == 0) logits[w] = s;
    __syncthreads();
    if (t == 0) {
        float mx = logits[0];
        #pragma unroll
        for (int e = 1; e < NE; e++) mx = fmaxf(mx, logits[e]);
        float p[NE], den = 0.f;
        #pragma unroll
        for (int e = 0; e < NE; e++) { p[e] = expf(logits[e] - mx); den += p[e]; }
        float inv = 1.f / den;
        int i0 = 0;
        #pragma unroll
        for (int e = 1; e < NE; e++) if (p[e] > p[i0]) i0 = e;
        int i1 = (i0 == 0) ? 1 : 0;
        #pragma unroll
        for (int e = 0; e < NE; e++) if (e != i0 && p[e] > p[i1]) i1 = e;
        int p0 = atomicAdd(&d_ecnt[i0], 1);
        int s0 = i0 * ECAP + p0;
        d_etok[s0] = n; d_ewt[s0] = p[i0] * inv; d_slot[2*n] = s0;
        int p1 = atomicAdd(&d_ecnt[i1], 1);
        int s1 = i1 * ECAP + p1;
        d_etok[s1] = n; d_ewt[s1] = p[i1] * inv; d_slot[2*n+1] = s1;
    }
}

// weight transposes, one launch: src [K][N] fp32 -> [N][K] fp16
__global__ void convT_all(const float* __restrict__ Wgs, const float* __restrict__ Wus,
                          const float* __restrict__ Wds, const float* __restrict__ Wge,
                          const float* __restrict__ Wue, const float* __restrict__ Wde) {
    int id = blockIdx.x;
    const float* src; __half* dh; int K, N, tile;
    if (id < 1024)      { src = Wgs; dh = d_Wgs; K = DIM; N = DS;  tile = id; }
    else if (id < 2048) { src = Wus; dh = d_Wus; K = DIM; N = DS;  tile = id - 1024; }
    else if (id < 3072) { src = Wds; dh = d_Wds; K = DS;  N = DIM; tile = id - 2048; }
    else if (id < 7168) {
        int l = id - 3072; int b = l >> 9; tile = l & 511; K = DIM; N = DE;
        src = Wge + (size_t)b * DIM * DE; dh = d_Wge + (size_t)b * DE * DIM;
    } else if (id < 11264) {
        int l = id - 7168; int b = l >> 9; tile = l & 511; K = DIM; N = DE;
        src = Wue + (size_t)b * DIM * DE; dh = d_Wue + (size_t)b * DE * DIM;
    } else {
        int l = id - 11264; int b = l >> 9; tile = l & 511; K = DE; N = DIM;
        src = Wde + (size_t)b * DE * DIM; dh = d_Wde + (size_t)b * DIM * DE;
    }
    int tilesX = N / 32;
    int n0 = (tile % tilesX) * 32, k0 = (tile / tilesX) * 32;
    __shared__ float t[32][33];
    int tx = threadIdx.x, ty = threadIdx.y;
    #pragma unroll
    for (int i = 0; i < 32; i += 8) t[ty + i][tx] = src[(size_t)(k0 + ty + i) * N + n0 + tx];
    __syncthreads();
    #pragma unroll
    for (int i = 0; i < 32; i += 8) {
        dh[(size_t)(n0 + ty + i) * K + k0 + tx] = __float2half(t[tx][ty + i]);
    }
}

__device__ __forceinline__ float silu(float g) { return g * (1.f / (1.f + expf(-g))); }

__global__ void combine_kernel(float* __restrict__ out) {
    int n = blockIdx.x;
    int t = threadIdx.x;
    int s0 = d_slot[2 * n], s1 = d_slot[2 * n + 1];
    float4* o4 = (float4*)(out + (size_t)n * DIM);
    const float4* r0 = (const float4*)(d_R + (size_t)s0 * DIM);
    const float4* r1 = (const float4*)(d_R + (size_t)s1 * DIM);
    float4 a = o4[t], b = r0[t], c = r1[t];
    a.x += b.x + c.x; a.y += b.y + c.y; a.z += b.z + c.z; a.w += b.w + c.w;
    o4[t] = a;
}

// ============================================================
// GEMMs: fp16 2-term. M-tile 64, 3 CTAs/SM (32KB/stage, 2 stages).
// ============================================================

// ---------------- hidden GEMM ----------------
// CTA tile M64 x N64 per matrix (g,u); 8 warps 2x4, warp 32x16 per matrix.
#define H_AH  0
#define H_AL  8192
#define H_BG  16384
#define H_BU  24576
#define H_STG 32768
#define H_TOT (2 * H_STG)

__global__ void __launch_bounds__(256, 3) hidden_gemm() {
    extern __shared__ char sm[];
    int tid = threadIdx.x, lane = tid & 31, wid = tid >> 5;
    int wm = wid >> 2, wn = wid & 3;
    int z = blockIdx.z, bx = blockIdx.x;
    int m0 = blockIdx.y * 64;
    bool routed = (z > 0);

    const __half *Bg, *Bu;
    __half *Hh, *Hl;
    int ldOut, cRowBase, mValid;
    const int K = DIM;

    int aRow = tid >> 2, aQ = tid & 3;        // A loader: 64 rows, 4 thr/row (32B each)
    int aRowLd;

    if (!routed) {
        Bg = d_Wgs; Bu = d_Wus;
        Hh = d_Hs_h; Hl = d_Hs_l; ldOut = DS;
        mValid = 64; cRowBase = m0;
        aRowLd = m0 + aRow;
    } else {
        if (bx >= DE / 64) return;
        int e = z - 1;
        int cnt = d_ecnt[e], off = e * ECAP;
        if (m0 >= cnt) return;
        size_t wb = (size_t)e * DE * DIM;
        Bg = d_Wge + wb; Bu = d_Wue + wb;
        Hh = d_Hr_h; Hl = d_Hr_l; ldOut = DE;
        mValid = cnt - m0; if (mValid > 64) mValid = 64;
        cRowBase = off + m0;
        int m = m0 + aRow; if (m > cnt - 1) m = cnt - 1;
        aRowLd = d_etok[off + m];
    }
    int n0 = bx * 64;

    uint32_t sbase = sm2u32(sm);
    const char* aGh = (const char*)(d_xh + (size_t)aRowLd * DIM) + aQ * 32;
    const char* aGl = (const char*)(d_xl + (size_t)aRowLd * DIM) + aQ * 32;
    const char* bgP = (const char*)(Bg + (size_t)(n0 + aRow) * K) + aQ * 32;
    const char* buP = (const char*)(Bu + (size_t)(n0 + aRow) * K) + aQ * 32;
    uint32_t sA[2];
    #pragma unroll
    for (int j = 0; j < 2; j++) sA[j] = SWZ((uint32_t)(aRow * 128 + aQ * 32 + j * 16));

    const int nChunks = K / 64;

    // prologue: stage 0 <- chunk 0
    {
        uint32_t sb = sbase;
        #pragma unroll
        for (int j = 0; j < 2; j++) {
            CPA16(sb + H_AH + sA[j], aGh + j * 16);
            CPA16(sb + H_AL + sA[j], aGl + j * 16);
            CPA16(sb + H_BG + sA[j], bgP + j * 16);
            CPA16(sb + H_BU + sA[j], buP + j * 16);
        }
        CPCOMMIT();
    }

    float ag[2][2][4], au[2][2][4];
    #pragma unroll
    for (int a = 0; a < 2; a++)
        #pragma unroll
        for (int b = 0; b < 2; b++)
            #pragma unroll
            for (int cR = 0; cR < 4; cR++) { ag[a][b][cR] = 0.f; au[a][b][cR] = 0.f; }

    int aRowB = wm * 32 + (lane & 15);
    uint32_t aCol = ((lane >> 4) & 1) * 16;
    int bRowB = wn * 16 + (lane & 7) + ((lane >> 4) << 3);
    uint32_t bCol = ((lane >> 3) & 1) * 16;

    for (int c = 0; c < nChunks; c++) {
        if (c + 1 < nChunks) {
            uint32_t sb = sbase + ((c + 1) & 1) * H_STG;
            int kb = (c + 1) * 128;
            #pragma unroll
            for (int j = 0; j < 2; j++) {
                CPA16(sb + H_AH + sA[j], aGh + kb + j * 16);
                CPA16(sb + H_AL + sA[j], aGl + kb + j * 16);
                CPA16(sb + H_BG + sA[j], bgP + kb + j * 16);
                CPA16(sb + H_BU + sA[j], buP + kb + j * 16);
            }
            CPCOMMIT();
            CPWAIT1();
        } else {
            CPWAIT0();
        }
        __syncthreads();

        uint32_t sb = sbase + (c & 1) * H_STG;
        #pragma unroll
        for (int ks = 0; ks < 4; ks++) {
            uint32_t bg[4], bu[4];
            {
                uint32_t rb = (uint32_t)(bRowB * 128 + ks * 32 + bCol);
                LDMX4(bg, sb + H_BG + SWZ(rb));
                LDMX4(bu, sb + H_BU + SWZ(rb));
            }
            #pragma unroll
            for (int mt = 0; mt < 2; mt++) {
                uint32_t ah[4], al[4];
                uint32_t rb = (uint32_t)((aRowB + mt * 16) * 128 + ks * 32 + aCol);
                LDMX4(ah, sb + H_AH + SWZ(rb));
                LDMX4(al, sb + H_AL + SWZ(rb));
                #pragma unroll
                for (int n8 = 0; n8 < 2; n8++) {
                    int j = n8 * 2;
                    MMAF16(ag[mt][n8], ah, bg[j], bg[j + 1]);
                    MMAF16(ag[mt][n8], al, bg[j], bg[j + 1]);
                    MMAF16(au[mt][n8], ah, bu[j], bu[j + 1]);
                    MMAF16(au[mt][n8], al, bu[j], bu[j + 1]);
                }
            }
        }
        __syncthreads();
    }

    #pragma unroll
    for (int mt = 0; mt < 2; mt++) {
        #pragma unroll
        for (int h = 0; h < 2; h++) {
            int rIn = wm * 32 + mt * 16 + (lane >> 2) + h * 8;
            if (rIn < mValid) {
                float wt = routed ? d_ewt[cRowBase + rIn] : 1.0f;
                size_t rowOff = (size_t)(cRowBase + rIn) * ldOut;
                #pragma unroll
                for (int n8 = 0; n8 < 2; n8++) {
                    int col = n0 + wn * 16 + n8 * 8 + (lane & 3) * 2;
                    float v0 = wt * silu(ag[mt][n8][h * 2 + 0]) * au[mt][n8][h * 2 + 0];
                    float v1 = wt * silu(ag[mt][n8][h * 2 + 1]) * au[mt][n8][h * 2 + 1];
                    __half h0, l0, h1, l1;
                    splitH(v0, h0, l0); splitH(v1, h1, l1);
                    __half2 hv; hv.x = h0; hv.y = h1;
                    __half2 lv; lv.x = l0; lv.y = l1;
                    *(__half2*)(Hh + rowOff + col) = hv;
                    *(__half2*)(Hl + rowOff + col) = lv;
                }
            }
        }
    }
}

// ---------------- down GEMM ----------------
// CTA tile M64 x N128; 8 warps 2x4, warp 32x32. z=0 dense -> out; z>0 routed -> R.
#define D_AH  0
#define D_AL  8192
#define D_B   16384
#define D_STG 32768
#define D_TOT (2 * D_STG)

__global__ void __launch_bounds__(256, 3) down_gemm(float* __restrict__ out) {
    extern __shared__ char sm[];
    int tid = threadIdx.x, lane = tid & 31, wid = tid >> 5;
    int wm = wid >> 2, wn = wid & 3;
    int z = blockIdx.z;
    int m0 = blockIdx.y * 64;
    bool routed = (z > 0);

    const __half *Ah, *Al, *B;
    float* C;
    int K, mValid, cRowBase, aRowLd;

    int aRow = tid >> 2, aQ = tid & 3;        // A: 64 rows, 4 thr/row
    int bRow = tid >> 1, bHalf = tid & 1;     // B: 128 rows, 2 thr/row

    if (!routed) {
        Ah = d_Hs_h; Al = d_Hs_l; K = DS;
        B = d_Wds;
        C = out;
        mValid = 64; cRowBase = m0;
        aRowLd = m0 + aRow;
    } else {
        int e = z - 1;
        int cnt = d_ecnt[e], off = e * ECAP;
        if (m0 >= cnt) return;
        Ah = d_Hr_h; Al = d_Hr_l; K = DE;
        B = d_Wde + (size_t)e * DIM * DE;
        C = d_R;
        mValid = cnt - m0; if (mValid > 64) mValid = 64;
        cRowBase = off + m0;
        int m = m0 + aRow; if (m > cnt - 1) m = cnt - 1;
        aRowLd = off + m;
    }
    int n0 = blockIdx.x * 128;

    uint32_t sbase = sm2u32(sm);
    const char* aGh = (const char*)(Ah + (size_t)aRowLd * K) + aQ * 32;
    const char* aGl = (const char*)(Al + (size_t)aRowLd * K) + aQ * 32;
    const char* bG  = (const char*)(B + (size_t)(n0 + bRow) * K) + bHalf * 64;
    uint32_t sA[2], sB[4];
    #pragma unroll
    for (int j = 0; j < 2; j++) sA[j] = SWZ((uint32_t)(aRow * 128 + aQ * 32 + j * 16));
    #pragma unroll
    for (int j = 0; j < 4; j++) sB[j] = SWZ((uint32_t)(bRow * 128 + bHalf * 64 + j * 16));

    int nChunks = K / 64;

    {
        uint32_t sb = sbase;
        #pragma unroll
        for (int j = 0; j < 2; j++) {
            CPA16(sb + D_AH + sA[j], aGh + j * 16);
            CPA16(sb + D_AL + sA[j], aGl + j * 16);
        }
        #pragma unroll
        for (int j = 0; j < 4; j++) CPA16(sb + D_B + sB[j], bG + j * 16);
        CPCOMMIT();
    }

    float acc[2][4][4];
    #pragma unroll
    for (int a = 0; a < 2; a++)
        #pragma unroll
        for (int b = 0; b < 4; b++)
            #pragma unroll
            for (int cR = 0; cR < 4; cR++) acc[a][b][cR] = 0.f;

    int aRowB = wm * 32 + (lane & 15);
    uint32_t aCol = ((lane >> 4) & 1) * 16;
    int bRowB = wn * 32 + (lane & 7) + ((lane >> 4) << 3);
    uint32_t bCol = ((lane >> 3) & 1) * 16;

    for (int c = 0; c < nChunks; c++) {
        if (c + 1 < nChunks) {
            uint32_t sb = sbase + ((c + 1) & 1) * D_STG;
            int kb = (c + 1) * 128;
            #pragma unroll
            for (int j = 0; j < 2; j++) {
                CPA16(sb + D_AH + sA[j], aGh + kb + j * 16);
                CPA16(sb + D_AL + sA[j], aGl + kb + j * 16);
            }
            #pragma unroll
            for (int j = 0; j < 4; j++) CPA16(sb + D_B + sB[j], bG + kb + j * 16);
            CPCOMMIT();
            CPWAIT1();
        } else {
            CPWAIT0();
        }
        __syncthreads();

        uint32_t sb = sbase + (c & 1) * D_STG;
        #pragma unroll
        for (int ks = 0; ks < 4; ks++) {
            uint32_t b[2][4];
            #pragma unroll
            for (int g = 0; g < 2; g++) {
                uint32_t rb = (uint32_t)((bRowB + g * 16) * 128 + ks * 32 + bCol);
                LDMX4(b[g], sb + D_B + SWZ(rb));
            }
            #pragma unroll
            for (int mt = 0; mt < 2; mt++) {
                uint32_t ah[4], al[4];
                uint32_t rb = (uint32_t)((aRowB + mt * 16) * 128 + ks * 32 + aCol);
                LDMX4(ah, sb + D_AH + SWZ(rb));
                LDMX4(al, sb + D_AL + SWZ(rb));
                #pragma unroll
                for (int n8 = 0; n8 < 4; n8++) {
                    int g = n8 >> 1, j = (n8 & 1) * 2;
                    MMAF16(acc[mt][n8], ah, b[g][j], b[g][j + 1]);
                    MMAF16(acc[mt][n8], al, b[g][j], b[g][j + 1]);
                }
            }
        }
        __syncthreads();
    }

    #pragma unroll
    for (int mt = 0; mt < 2; mt++) {
        #pragma unroll
        for (int h = 0; h < 2; h++) {
            int rIn = wm * 32 + mt * 16 + (lane >> 2) + h * 8;
            if (rIn < mValid) {
                float* p = C + (size_t)(cRowBase + rIn) * DIM + n0 + wn * 32 + (lane & 3) * 2;
                #pragma unroll
                for (int n8 = 0; n8 < 4; n8++) {
                    float2 v; v.x = acc[mt][n8][h * 2 + 0]; v.y = acc[mt][n8][h * 2 + 1];
                    *(float2*)(p + n8 * 8) = v;
                }
            }
        }
    }
}

// ----------------- launch -----------------
extern "C" void kernel_launch(void* const* d_in, const int* in_sizes, int n_in,
                              void* d_out, int out_size) {
    const float* x   = (const float*)d_in[0];
    const float* Wg  = (const float*)d_in[1];
    const float* Wge = (const float*)d_in[2];
    const float* Wue = (const float*)d_in[3];
    const float* Wde = (const float*)d_in[4];
    const float* Wgs = (const float*)d_in[5];
    const float* Wus = (const float*)d_in[6];
    const float* Wds = (const float*)d_in[7];
    float* out = (float*)d_out;

    cudaFuncSetAttribute(hidden_gemm, cudaFuncAttributeMaxDynamicSharedMemorySize, H_TOT);
    cudaFuncSetAttribute(down_gemm,   cudaFuncAttributeMaxDynamicSharedMemorySize, D_TOT);

    void* ecnt_ptr;
    cudaGetSymbolAddress(&ecnt_ptr, d_ecnt);
    cudaMemsetAsync(ecnt_ptr, 0, NE * sizeof(int), 0);

    convT_all<<<15360, dim3(32, 8)>>>(Wgs, Wus, Wds, Wge, Wue, Wde);     // 1
    gate_kernel<<<N_TOK, 256>>>(x, Wg);                                  // 2
    hidden_gemm<<<dim3(16, 32, 9), 256, H_TOT>>>();                      // 3
    down_gemm<<<dim3(8, 32, 9), 256, D_TOT>>>(out);                      // 4  <- profiled
    combine_kernel<<<N_TOK, 256>>>(out);                                 // 5
}

// round 11
// speedup vs baseline: 5.2212x; 1.2856x over previous
#include <cuda_runtime.h>
#include <cuda_fp16.h>
#include <math.h>
#include <stdint.h>

#define N_TOK 2048
#define DIM   1024
#define DE    512
#define DS    1024
#define NE    8
#define NSLOT (N_TOK * 2)
#define ECAP  2048

// ----------------- scratch (device globals; no allocs) -----------------
__device__ int   d_ecnt[NE];                 // zeroed via cudaMemsetAsync
__device__ int   d_etok[NE * ECAP];
__device__ float d_ewt [NE * ECAP];
__device__ int   d_slot[NSLOT];

__device__ __half d_x  [N_TOK * DIM];                     // x fp16
__device__ __half d_Wgs[DS * DIM];                        // weights fp16, [N][K]
__device__ __half d_Wus[DS * DIM];
__device__ __half d_Wds[DIM * DS];
__device__ __half d_Wge[NE * DE * DIM];
__device__ __half d_Wue[NE * DE * DIM];
__device__ __half d_Wde[NE * DIM * DE];

__device__ __half d_Hs[N_TOK * DS];
__device__ __half d_Hr[NE * ECAP * DE];
__device__ float d_R [NE * ECAP * DIM];

// ----------------- asm helpers -----------------
__device__ __forceinline__ uint32_t sm2u32(const void* p) {
    uint32_t a;
    asm("{ .reg .u64 t; cvta.to.shared.u64 t, %1; cvt.u32.u64 %0, t; }" : "=r"(a) : "l"(p));
    return a;
}
#define SWZ(o) ((o) ^ (((o) >> 3) & 0x70))

#define CPA16(s, g)  asm volatile("cp.async.cg.shared.global [%0], [%1], 16;" :: "r"(s), "l"(g))
#define CPCOMMIT()   asm volatile("cp.async.commit_group;" ::: "memory")
#define CPWAIT2()    asm volatile("cp.async.wait_group 2;" ::: "memory")
#define CPWAIT1()    asm volatile("cp.async.wait_group 1;" ::: "memory")
#define CPWAIT0()    asm volatile("cp.async.wait_group 0;" ::: "memory")

#define LDMX4(r, a) \
    asm volatile("ldmatrix.sync.aligned.m8n8.x4.shared.b16 {%0,%1,%2,%3}, [%4];" \
        : "=r"((r)[0]), "=r"((r)[1]), "=r"((r)[2]), "=r"((r)[3]) : "r"(a))

#define MMAF16(c, a, b0, b1) \
    asm volatile("mma.sync.aligned.m16n8k16.row.col.f32.f16.f16.f32 " \
        "{%0,%1,%2,%3},{%4,%5,%6,%7},{%8,%9},{%0,%1,%2,%3};" \
        : "+f"((c)[0]), "+f"((c)[1]), "+f"((c)[2]), "+f"((c)[3]) \
        : "r"((a)[0]), "r"((a)[1]), "r"((a)[2]), "r"((a)[3]), "r"(b0), "r"(b1))

// ----------------- gate + convX + routing (fused) -----------------
__global__ void gate_kernel(const float* __restrict__ x, const float* __restrict__ Wg) {
    int n = blockIdx.x;
    int t = threadIdx.x;
    __shared__ float xs[DIM];
    __shared__ float logits[NE];
    float4 v = ((const float4*)(x + (size_t)n * DIM))[t];
    ((float4*)xs)[t] = v;
    {
        __half2 a, b;
        a.x = __float2half(v.x); a.y = __float2half(v.y);
        b.x = __float2half(v.z); b.y = __float2half(v.w);
        size_t o = (size_t)n * DIM + t * 4;
        *(__half2*)(d_x + o) = a; *(__half2*)(d_x + o + 2) = b;
    }
    __syncthreads();
    int w = t >> 5, l = t & 31;
    float s = 0.f;
    for (int d = l; d < DIM; d += 32) s += xs[d] * Wg[d * NE + w];
    #pragma unroll
    for (int o = 16; o; o >>= 1) s += __shfl_xor_sync(0xffffffffu, s, o);
    if (l == 0) logits[w] = s;
    __syncthreads();
    if (t == 0) {
        float mx = logits[0];
        #pragma unroll
        for (int e = 1; e < NE; e++) mx = fmaxf(mx, logits[e]);
        float p[NE], den = 0.f;
        #pragma unroll
        for (int e = 0; e < NE; e++) { p[e] = expf(logits[e] - mx); den += p[e]; }
        float inv = 1.f / den;
        int i0 = 0;
        #pragma unroll
        for (int e = 1; e < NE; e++) if (p[e] > p[i0]) i0 = e;
        int i1 = (i0 == 0) ? 1 : 0;
        #pragma unroll
        for (int e = 0; e < NE; e++) if (e != i0 && p[e] > p[i1]) i1 = e;
        int p0 = atomicAdd(&d_ecnt[i0], 1);
        int s0 = i0 * ECAP + p0;
        d_etok[s0] = n; d_ewt[s0] = p[i0] * inv; d_slot[2*n] = s0;
        int p1 = atomicAdd(&d_ecnt[i1], 1);
        int s1 = i1 * ECAP + p1;
        d_etok[s1] = n; d_ewt[s1] = p[i1] * inv; d_slot[2*n+1] = s1;
    }
}

// weight transposes, one launch: src [K][N] fp32 -> [N][K] fp16
__global__ void convT_all(const float* __restrict__ Wgs, const float* __restrict__ Wus,
                          const float* __restrict__ Wds, const float* __restrict__ Wge,
                          const float* __restrict__ Wue, const float* __restrict__ Wde) {
    int id = blockIdx.x;
    const float* src; __half* dh; int K, N, tile;
    if (id < 1024)      { src = Wgs; dh = d_Wgs; K = DIM; N = DS;  tile = id; }
    else if (id < 2048) { src = Wus; dh = d_Wus; K = DIM; N = DS;  tile = id - 1024; }
    else if (id < 3072) { src = Wds; dh = d_Wds; K = DS;  N = DIM; tile = id - 2048; }
    else if (id < 7168) {
        int l = id - 3072; int b = l >> 9; tile = l & 511; K = DIM; N = DE;
        src = Wge + (size_t)b * DIM * DE; dh = d_Wge + (size_t)b * DE * DIM;
    } else if (id < 11264) {
        int l = id - 7168; int b = l >> 9; tile = l & 511; K = DIM; N = DE;
        src = Wue + (size_t)b * DIM * DE; dh = d_Wue + (size_t)b * DE * DIM;
    } else {
        int l = id - 11264; int b = l >> 9; tile = l & 511; K = DE; N = DIM;
        src = Wde + (size_t)b * DE * DIM; dh = d_Wde + (size_t)b * DIM * DE;
    }
    int tilesX = N / 32;
    int n0 = (tile % tilesX) * 32, k0 = (tile / tilesX) * 32;
    __shared__ float t[32][33];
    int tx = threadIdx.x, ty = threadIdx.y;
    #pragma unroll
    for (int i = 0; i < 32; i += 8) t[ty + i][tx] = src[(size_t)(k0 + ty + i) * N + n0 + tx];
    __syncthreads();
    #pragma unroll
    for (int i = 0; i < 32; i += 8) {
        dh[(size_t)(n0 + ty + i) * K + k0 + tx] = __float2half(t[tx][ty + i]);
    }
}

__device__ __forceinline__ float silu(float g) { return g * (1.f / (1.f + expf(-g))); }

__global__ void combine_kernel(float* __restrict__ out) {
    int n = blockIdx.x;
    int t = threadIdx.x;
    int s0 = d_slot[2 * n], s1 = d_slot[2 * n + 1];
    float4* o4 = (float4*)(out + (size_t)n * DIM);
    const float4* r0 = (const float4*)(d_R + (size_t)s0 * DIM);
    const float4* r1 = (const float4*)(d_R + (size_t)s1 * DIM);
    float4 a = o4[t], b = r0[t], c = r1[t];
    a.x += b.x + c.x; a.y += b.y + c.y; a.z += b.z + c.z; a.w += b.w + c.w;
    o4[t] = a;
}

// ============================================================
// GEMMs: pure fp16 (A and B single fp16, fp32 accum).
// M-tile 64, 24KB/stage, 3-stage cp.async, 3 CTAs/SM.
// ============================================================

// ---------------- hidden GEMM ----------------
// CTA tile M64 x N64 per matrix (g,u); 8 warps 2x4, warp 32x16 per matrix.
#define H_A   0
#define H_BG  8192
#define H_BU  16384
#define H_STG 24576
#define H_TOT (3 * H_STG)

__global__ void __launch_bounds__(256, 3) hidden_gemm() {
    extern __shared__ char sm[];
    int tid = threadIdx.x, lane = tid & 31, wid = tid >> 5;
    int wm = wid >> 2, wn = wid & 3;
    int z = blockIdx.z, bx = blockIdx.x;
    int m0 = blockIdx.y * 64;
    bool routed = (z > 0);

    const __half *Bg, *Bu;
    __half *H;
    int ldOut, cRowBase, mValid;
    const int K = DIM;

    int aRow = tid >> 2, aQ = tid & 3;        // loaders: 64 rows, 4 thr/row (32B each)
    int aRowLd;

    if (!routed) {
        Bg = d_Wgs; Bu = d_Wus;
        H = d_Hs; ldOut = DS;
        mValid = 64; cRowBase = m0;
        aRowLd = m0 + aRow;
    } else {
        if (bx >= DE / 64) return;
        int e = z - 1;
        int cnt = d_ecnt[e], off = e * ECAP;
        if (m0 >= cnt) return;
        size_t wb = (size_t)e * DE * DIM;
        Bg = d_Wge + wb; Bu = d_Wue + wb;
        H = d_Hr; ldOut = DE;
        mValid = cnt - m0; if (mValid > 64) mValid = 64;
        cRowBase = off + m0;
        int m = m0 + aRow; if (m > cnt - 1) m = cnt - 1;
        aRowLd = d_etok[off + m];
    }
    int n0 = bx * 64;

    uint32_t sbase = sm2u32(sm);
    const char* aG  = (const char*)(d_x + (size_t)aRowLd * DIM) + aQ * 32;
    const char* bgP = (const char*)(Bg + (size_t)(n0 + aRow) * K) + aQ * 32;
    const char* buP = (const char*)(Bu + (size_t)(n0 + aRow) * K) + aQ * 32;
    uint32_t sA[2];
    #pragma unroll
    for (int j = 0; j < 2; j++) sA[j] = SWZ((uint32_t)(aRow * 128 + aQ * 32 + j * 16));

    const int nChunks = K / 64;

    // prologue: stages 0,1 <- chunks 0,1
    #pragma unroll
    for (int c = 0; c < 2; c++) {
        uint32_t sb = sbase + c * H_STG;
        int kb = c * 128;
        #pragma unroll
        for (int j = 0; j < 2; j++) {
            CPA16(sb + H_A  + sA[j], aG  + kb + j * 16);
            CPA16(sb + H_BG + sA[j], bgP + kb + j * 16);
            CPA16(sb + H_BU + sA[j], buP + kb + j * 16);
        }
        CPCOMMIT();
    }

    float ag[2][2][4], au[2][2][4];
    #pragma unroll
    for (int a = 0; a < 2; a++)
        #pragma unroll
        for (int b = 0; b < 2; b++)
            #pragma unroll
            for (int cR = 0; cR < 4; cR++) { ag[a][b][cR] = 0.f; au[a][b][cR] = 0.f; }

    int aRowB = wm * 32 + (lane & 15);
    uint32_t aCol = ((lane >> 4) & 1) * 16;
    int bRowB = wn * 16 + (lane & 7) + ((lane >> 4) << 3);
    uint32_t bCol = ((lane >> 3) & 1) * 16;

    int st = 0;
    for (int c = 0; c < nChunks; c++) {
        if (c + 2 < nChunks) {
            int pf = (st == 0) ? 2 : st - 1;      // (c+2)%3
            uint32_t sb = sbase + pf * H_STG;
            int kb = (c + 2) * 128;
            #pragma unroll
            for (int j = 0; j < 2; j++) {
                CPA16(sb + H_A  + sA[j], aG  + kb + j * 16);
                CPA16(sb + H_BG + sA[j], bgP + kb + j * 16);
                CPA16(sb + H_BU + sA[j], buP + kb + j * 16);
            }
            CPCOMMIT();
            CPWAIT2();
        } else if (c + 1 < nChunks) {
            CPWAIT1();
        } else {
            CPWAIT0();
        }
        __syncthreads();

        uint32_t sb = sbase + st * H_STG;
        #pragma unroll
        for (int ks = 0; ks < 4; ks++) {
            uint32_t bg[4], bu[4];
            {
                uint32_t rb = (uint32_t)(bRowB * 128 + ks * 32 + bCol);
                LDMX4(bg, sb + H_BG + SWZ(rb));
                LDMX4(bu, sb + H_BU + SWZ(rb));
            }
            #pragma unroll
            for (int mt = 0; mt < 2; mt++) {
                uint32_t a[4];
                uint32_t rb = (uint32_t)((aRowB + mt * 16) * 128 + ks * 32 + aCol);
                LDMX4(a, sb + H_A + SWZ(rb));
                #pragma unroll
                for (int n8 = 0; n8 < 2; n8++) {
                    int j = n8 * 2;
                    MMAF16(ag[mt][n8], a, bg[j], bg[j + 1]);
                    MMAF16(au[mt][n8], a, bu[j], bu[j + 1]);
                }
            }
        }
        __syncthreads();
        st = (st == 2) ? 0 : st + 1;
    }

    #pragma unroll
    for (int mt = 0; mt < 2; mt++) {
        #pragma unroll
        for (int h = 0; h < 2; h++) {
            int rIn = wm * 32 + mt * 16 + (lane >> 2) + h * 8;
            if (rIn < mValid) {
                float wt = routed ? d_ewt[cRowBase + rIn] : 1.0f;
                size_t rowOff = (size_t)(cRowBase + rIn) * ldOut;
                #pragma unroll
                for (int n8 = 0; n8 < 2; n8++) {
                    int col = n0 + wn * 16 + n8 * 8 + (lane & 3) * 2;
                    float v0 = wt * silu(ag[mt][n8][h * 2 + 0]) * au[mt][n8][h * 2 + 0];
                    float v1 = wt * silu(ag[mt][n8][h * 2 + 1]) * au[mt][n8][h * 2 + 1];
                    __half2 hv; hv.x = __float2half(v0); hv.y = __float2half(v1);
                    *(__half2*)(H + rowOff + col) = hv;
                }
            }
        }
    }
}

// ---------------- down GEMM ----------------
// CTA tile M64 x N128; 8 warps 2x4, warp 32x32. z=0 dense -> out; z>0 routed -> R.
#define D_A   0
#define D_B   8192
#define D_STG 24576
#define D_TOT (3 * D_STG)

__global__ void __launch_bounds__(256, 3) down_gemm(float* __restrict__ out) {
    extern __shared__ char sm[];
    int tid = threadIdx.x, lane = tid & 31, wid = tid >> 5;
    int wm = wid >> 2, wn = wid & 3;
    int z = blockIdx.z;
    int m0 = blockIdx.y * 64;
    bool routed = (z > 0);

    const __half *A, *B;
    float* C;
    int K, mValid, cRowBase, aRowLd;

    int aRow = tid >> 2, aQ = tid & 3;        // A: 64 rows, 4 thr/row
    int bRow = tid >> 1, bHalf = tid & 1;     // B: 128 rows, 2 thr/row

    if (!routed) {
        A = d_Hs; K = DS;
        B = d_Wds;
        C = out;
        mValid = 64; cRowBase = m0;
        aRowLd = m0 + aRow;
    } else {
        int e = z - 1;
        int cnt = d_ecnt[e], off = e * ECAP;
        if (m0 >= cnt) return;
        A = d_Hr; K = DE;
        B = d_Wde + (size_t)e * DIM * DE;
        C = d_R;
        mValid = cnt - m0; if (mValid > 64) mValid = 64;
        cRowBase = off + m0;
        int m = m0 + aRow; if (m > cnt - 1) m = cnt - 1;
        aRowLd = off + m;
    }
    int n0 = blockIdx.x * 128;

    uint32_t sbase = sm2u32(sm);
    const char* aG = (const char*)(A + (size_t)aRowLd * K) + aQ * 32;
    const char* bG = (const char*)(B + (size_t)(n0 + bRow) * K) + bHalf * 64;
    uint32_t sA[2], sB[4];
    #pragma unroll
    for (int j = 0; j < 2; j++) sA[j] = SWZ((uint32_t)(aRow * 128 + aQ * 32 + j * 16));
    #pragma unroll
    for (int j = 0; j < 4; j++) sB[j] = SWZ((uint32_t)(bRow * 128 + bHalf * 64 + j * 16));

    int nChunks = K / 64;

    #pragma unroll
    for (int c = 0; c < 2; c++) {
        uint32_t sb = sbase + c * D_STG;
        int kb = c * 128;
        #pragma unroll
        for (int j = 0; j < 2; j++) CPA16(sb + D_A + sA[j], aG + kb + j * 16);
        #pragma unroll
        for (int j = 0; j < 4; j++) CPA16(sb + D_B + sB[j], bG + kb + j * 16);
        CPCOMMIT();
    }

    float acc[2][4][4];
    #pragma unroll
    for (int a = 0; a < 2; a++)
        #pragma unroll
        for (int b = 0; b < 4; b++)
            #pragma unroll
            for (int cR = 0; cR < 4; cR++) acc[a][b][cR] = 0.f;

    int aRowB = wm * 32 + (lane & 15);
    uint32_t aCol = ((lane >> 4) & 1) * 16;
    int bRowB = wn * 32 + (lane & 7) + ((lane >> 4) << 3);
    uint32_t bCol = ((lane >> 3) & 1) * 16;

    int st = 0;
    for (int c = 0; c < nChunks; c++) {
        if (c + 2 < nChunks) {
            int pf = (st == 0) ? 2 : st - 1;
            uint32_t sb = sbase + pf * D_STG;
            int kb = (c + 2) * 128;
            #pragma unroll
            for (int j = 0; j < 2; j++) CPA16(sb + D_A + sA[j], aG + kb + j * 16);
            #pragma unroll
            for (int j = 0; j < 4; j++) CPA16(sb + D_B + sB[j], bG + kb + j * 16);
            CPCOMMIT();
            CPWAIT2();
        } else if (c + 1 < nChunks) {
            CPWAIT1();
        } else {
            CPWAIT0();
        }
        __syncthreads();

        uint32_t sb = sbase + st * D_STG;
        #pragma unroll
        for (int ks = 0; ks < 4; ks++) {
            uint32_t b[2][4];
            #pragma unroll
            for (int g = 0; g < 2; g++) {
                uint32_t rb = (uint32_t)((bRowB + g * 16) * 128 + ks * 32 + bCol);
                LDMX4(b[g], sb + D_B + SWZ(rb));
            }
            #pragma unroll
            for (int mt = 0; mt < 2; mt++) {
                uint32_t a[4];
                uint32_t rb = (uint32_t)((aRowB + mt * 16) * 128 + ks * 32 + aCol);
                LDMX4(a, sb + D_A + SWZ(rb));
                #pragma unroll
                for (int n8 = 0; n8 < 4; n8++) {
                    int g = n8 >> 1, j = (n8 & 1) * 2;
                    MMAF16(acc[mt][n8], a, b[g][j], b[g][j + 1]);
                }
            }
        }
        __syncthreads();
        st = (st == 2) ? 0 : st + 1;
    }

    #pragma unroll
    for (int mt = 0; mt < 2; mt++) {
        #pragma unroll
        for (int h = 0; h < 2; h++) {
            int rIn = wm * 32 + mt * 16 + (lane >> 2) + h * 8;
            if (rIn < mValid) {
                float* p = C + (size_t)(cRowBase + rIn) * DIM + n0 + wn * 32 + (lane & 3) * 2;
                #pragma unroll
                for (int n8 = 0; n8 < 4; n8++) {
                    float2 v; v.x = acc[mt][n8][h * 2 + 0]; v.y = acc[mt][n8][h * 2 + 1];
                    *(float2*)(p + n8 * 8) = v;
                }
            }
        }
    }
}

// ----------------- launch -----------------
extern "C" void kernel_launch(void* const* d_in, const int* in_sizes, int n_in,
                              void* d_out, int out_size) {
    const float* x   = (const float*)d_in[0];
    const float* Wg  = (const float*)d_in[1];
    const float* Wge = (const float*)d_in[2];
    const float* Wue = (const float*)d_in[3];
    const float* Wde = (const float*)d_in[4];
    const float* Wgs = (const float*)d_in[5];
    const float* Wus = (const float*)d_in[6];
    const float* Wds = (const float*)d_in[7];
    float* out = (float*)d_out;

    cudaFuncSetAttribute(hidden_gemm, cudaFuncAttributeMaxDynamicSharedMemorySize, H_TOT);
    cudaFuncSetAttribute(down_gemm,   cudaFuncAttributeMaxDynamicSharedMemorySize, D_TOT);

    void* ecnt_ptr;
    cudaGetSymbolAddress(&ecnt_ptr, d_ecnt);
    cudaMemsetAsync(ecnt_ptr, 0, NE * sizeof(int), 0);

    convT_all<<<15360, dim3(32, 8)>>>(Wgs, Wus, Wds, Wge, Wue, Wde);     // 1
    gate_kernel<<<N_TOK, 256>>>(x, Wg);                                  // 2
    hidden_gemm<<<dim3(16, 32, 9), 256, H_TOT>>>();                      // 3
    down_gemm<<<dim3(8, 32, 9), 256, D_TOT>>>(out);                      // 4  <- profiled
    combine_kernel<<<N_TOK, 256>>>(out);                                 // 5
}